// round 12
// baseline (speedup 1.0000x reference)
#include <cuda_runtime.h>
#include <cuda_fp16.h>
#include <cstdint>

#define B_ 4
#define T_ 2048
#define C_ 1024
#define H_ 16
#define D_ 64
#define M_ (B_*T_)   /* 8192 */

// ---------------- device scratch (fp16) ----------------------------------------
__device__ __half g_xh[(size_t)M_*C_];
__device__ __half g_xl[(size_t)M_*C_];
__device__ __half g_wa[(size_t)C_*3*C_];
__device__ __half g_wp[(size_t)C_*C_];
__device__ __half g_yh[(size_t)M_*C_];
__device__ __half g_qh[(size_t)M_*C_];
__device__ __half g_ql[(size_t)M_*C_];
__device__ __half g_k[(size_t)M_*C_];
__device__ __half g_v[(size_t)M_*C_];

// ---------------- helpers ------------------------------------------------------
__device__ __forceinline__ uint32_t s2u(const void* p) {
    return (uint32_t)__cvta_generic_to_shared(p);
}
__device__ __forceinline__ void cpa16(uint32_t dst, const void* src) {
    asm volatile("cp.async.cg.shared.global [%0], [%1], 16;" :: "r"(dst), "l"(src));
}
#define CP_COMMIT() asm volatile("cp.async.commit_group;" ::: "memory")
#define CP_WAIT2()  asm volatile("cp.async.wait_group 2;" ::: "memory")

#define LDM_X4(r, addr) \
    asm volatile("ldmatrix.sync.aligned.m8n8.x4.shared.b16 {%0,%1,%2,%3},[%4];" \
        : "=r"((r)[0]), "=r"((r)[1]), "=r"((r)[2]), "=r"((r)[3]) : "r"(addr))
#define LDM_X4T(r, addr) \
    asm volatile("ldmatrix.sync.aligned.m8n8.x4.trans.shared.b16 {%0,%1,%2,%3},[%4];" \
        : "=r"((r)[0]), "=r"((r)[1]), "=r"((r)[2]), "=r"((r)[3]) : "r"(addr))

#define MMA16816(d, a, b) \
    asm volatile("mma.sync.aligned.m16n8k16.row.col.f32.f16.f16.f32 " \
        "{%0,%1,%2,%3},{%4,%5,%6,%7},{%8,%9},{%0,%1,%2,%3};" \
        : "+f"((d)[0]), "+f"((d)[1]), "+f"((d)[2]), "+f"((d)[3]) \
        : "r"((a)[0]), "r"((a)[1]), "r"((a)[2]), "r"((a)[3]), \
          "r"((b)[0]), "r"((b)[1]))

__device__ __forceinline__ float ex2f(float x) {
    float y;
    asm("ex2.approx.f32 %0, %1;" : "=f"(y) : "f"(x));
    return y;
}

__device__ __forceinline__ uint32_t pack_h2(float a, float b) {
    __half2 v = __floats2half2_rn(a, b);
    return *(uint32_t*)&v;
}
__device__ __forceinline__ uint32_t pack_h2_lo(float a, float b, uint32_t hibits) {
    __half2 h = *(__half2*)&hibits;
    __half2 v;
    v.x = __float2half_rn(a - __half2float(h.x));
    v.y = __float2half_rn(b - __half2float(h.y));
    return *(uint32_t*)&v;
}
__device__ __forceinline__ void store_split2h(
    __half* ph, __half* pl, float a, float b)
{
    uint32_t hi = pack_h2(a, b);
    uint32_t lo = pack_h2_lo(a, b, hi);
    *(uint32_t*)ph = hi;
    *(uint32_t*)pl = lo;
}

// ---------------- mbarrier helpers ----------------------------------------------
#define MBARRIER_INIT(mbar, count) \
    asm volatile("mbarrier.init.shared.b64 [%0], %1;" \
        :: "r"((uint32_t)(mbar)), "r"((uint32_t)(count)) : "memory")

#define MBARRIER_ARRIVE(mbar) \
    asm volatile("mbarrier.arrive.shared.b64 _, [%0];" \
        :: "r"((uint32_t)(mbar)) : "memory")

// .noinc is load-bearing: default variant increments pending count first
// (net-zero per call) and the phase never completes -> hang (R11).
#define CPASYNC_MBAR_ARRIVE(mbar) \
    asm volatile("cp.async.mbarrier.arrive.noinc.shared.b64 [%0];" \
        :: "r"((uint32_t)(mbar)) : "memory")

#define MBARRIER_WAIT_PARITY(mbar_addr, phase_parity) do { \
    uint32_t _mbar = (uint32_t)(mbar_addr); \
    uint32_t _parity = (uint32_t)(phase_parity); \
    uint32_t _done; \
    asm volatile( \
        "{\n\t.reg .pred p;\n\t" \
        "mbarrier.try_wait.parity.acquire.cta.shared::cta.b64 p, [%1], %2;\n\t" \
        "selp.b32 %0, 1, 0, p;\n\t}" \
        : "=r"(_done) : "r"(_mbar), "r"(_parity) : "memory"); \
    if (!_done) { \
        asm volatile( \
            "{\n\t.reg .pred P1;\n\t" \
            "WAIT_LOOP_%=:\n\t" \
            "mbarrier.try_wait.parity.acquire.cta.shared::cta.b64 P1, [%0], %1, 0x989680;\n\t" \
            "@P1 bra.uni WAIT_DONE_%=;\n\t" \
            "bra.uni WAIT_LOOP_%=;\n\t" \
            "WAIT_DONE_%=:\n\t}" \
            :: "r"(_mbar), "r"(_parity) : "memory"); \
    } \
} while(0)

// q pre-scale: 1/sqrt(D) * log2(e)
#define QSCALE 0.1803368801111306f

// ---------------- merged preprocessing ------------------------------------------
#define NX  (M_*C_/4)
#define NWA (3*C_*C_/4)
#define NWP (C_*C_/4)

__global__ void preprocess_kernel(const float* __restrict__ x,
                                  const float* __restrict__ wa,
                                  const float* __restrict__ wp)
{
    int i = blockIdx.x * blockDim.x + threadIdx.x;
    if (i < NX) {
        float4 v = ((const float4*)x)[i];
        uint32_t h0 = pack_h2(v.x, v.y), h1 = pack_h2(v.z, v.w);
        uint32_t l0 = pack_h2_lo(v.x, v.y, h0), l1 = pack_h2_lo(v.z, v.w, h1);
        ((uint2*)g_xh)[i] = make_uint2(h0, h1);
        ((uint2*)g_xl)[i] = make_uint2(l0, l1);
    } else if (i < NX + NWA) {
        int j = i - NX;
        float4 v = ((const float4*)wa)[j];
        ((uint2*)g_wa)[j] = make_uint2(pack_h2(v.x, v.y), pack_h2(v.z, v.w));
    } else if (i < NX + NWA + NWP) {
        int j = i - NX - NWA;
        float4 v = ((const float4*)wp)[j];
        ((uint2*)g_wp)[j] = make_uint2(pack_h2(v.x, v.y), pack_h2(v.z, v.w));
    }
}

// ---------------- fp16 GEMM, BK=16, 4-stage (R8/R10-measured pipeline) ----------
#define BM 128
#define BN 128
#define BK 16
#define AST 24
#define BST 136
#define KTILES (C_/BK)          /* 64 */
#define STAGES 4
#define ASZ (BM*AST*2)
#define BSZ (BK*BST*2)
#define STG (2*ASZ + BSZ)
#define GEMM_SMEM (STAGES*STG)  /* 66560 B */

template<bool SCATTER, int NPROD>
__global__ __launch_bounds__(256, 2) void gemm_fp16(
    const float* __restrict__ bias, float* __restrict__ out, int N)
{
    extern __shared__ char dsm[];
    const uint32_t base = s2u(dsm);

    const __half* Agh = SCATTER ? g_xh : g_yh;
    const __half* Agl = SCATTER ? g_xl : g_yh;
    const __half* Bg  = SCATTER ? g_wa : g_wp;

    const int K = C_;
    const int tid  = threadIdx.x;
    const int lane = tid & 31, wid = tid >> 5;
    const int wr = wid >> 1, wc = wid & 1;
    const int row0 = blockIdx.y * BM, col0 = blockIdx.x * BN;

    const int rA = tid >> 1, cA = tid & 1;
    const int rB = tid >> 4, cB = tid & 15;

    const __half* srcAh = Agh + (size_t)(row0 + rA) * K + cA * 8;
    const __half* srcAl = Agl + (size_t)(row0 + rA) * K + cA * 8;
    const __half* srcB  = Bg  + (size_t)rB * N + col0 + cB * 8;

    const uint32_t offA = (uint32_t)(rA*AST + cA*8) * 2;
    const uint32_t offB = (uint32_t)(rB*BST + cB*8) * 2;

    auto load_stage = [&](int kt, int buf) {
        const uint32_t sb = base + buf * STG;
        cpa16(sb + offA, srcAh + kt * BK);
        if (NPROD == 2)
            cpa16(sb + ASZ + offA, srcAl + kt * BK);
        cpa16(sb + 2*ASZ + offB, srcB + (size_t)kt * BK * N);
    };

    const int lm = lane & 15, lh = lane >> 4;
    const uint32_t aOff = (uint32_t)((wr*32 + lm) * AST + lh * 8) * 2;
    const uint32_t bOff = (uint32_t)(lm * BST + (wc*64 + lh*8)) * 2;

    float acc[2][8][4];
#pragma unroll
    for (int mi = 0; mi < 2; mi++)
#pragma unroll
        for (int ni = 0; ni < 8; ni++)
#pragma unroll
            for (int r = 0; r < 4; r++) acc[mi][ni][r] = 0.f;

    auto compute = [&](int buf) {
        const uint32_t sb = base + buf * STG;
        const uint32_t aH = sb + aOff;
        const uint32_t aL = sb + ASZ + aOff;
        const uint32_t bB = sb + 2*ASZ + bOff;
        uint32_t ah[2][4], al[2][4], bb[8][2], r[4];
#pragma unroll
        for (int mi = 0; mi < 2; mi++) LDM_X4(ah[mi], aH + mi * (16*AST*2));
#pragma unroll
        for (int g = 0; g < 4; g++) {
            LDM_X4T(r, bB + g * 32);
            bb[2*g][0]   = r[0]; bb[2*g][1]   = r[1];
            bb[2*g+1][0] = r[2]; bb[2*g+1][1] = r[3];
        }
#pragma unroll
        for (int mi = 0; mi < 2; mi++)
#pragma unroll
            for (int ni = 0; ni < 8; ni++) MMA16816(acc[mi][ni], ah[mi], bb[ni]);
        if (NPROD == 2) {
#pragma unroll
            for (int mi = 0; mi < 2; mi++) LDM_X4(al[mi], aL + mi * (16*AST*2));
#pragma unroll
            for (int mi = 0; mi < 2; mi++)
#pragma unroll
                for (int ni = 0; ni < 8; ni++) MMA16816(acc[mi][ni], al[mi], bb[ni]);
        }
    };

#pragma unroll
    for (int s = 0; s < STAGES - 1; s++) {
        load_stage(s, s);
        CP_COMMIT();
    }

#pragma unroll 1
    for (int kt = 0; kt < KTILES; kt++) {
        CP_WAIT2();
        __syncthreads();
        if (kt + STAGES - 1 < KTILES)
            load_stage(kt + STAGES - 1, (kt + STAGES - 1) & (STAGES - 1));
        CP_COMMIT();
        compute(kt & (STAGES - 1));
    }

    // ---------------- epilogue ----------------
    const int ncol0 = col0 + wc * 64;
    const int which = SCATTER ? (ncol0 / C_) : 0;
    const int c0 = ncol0 % C_;
    const int hh = c0 / D_;

#pragma unroll
    for (int ni = 0; ni < 8; ni++) {
        const int n = ncol0 + ni*8 + (lane & 3) * 2;
        const float b0 = bias[n], b1 = bias[n + 1];
        if (SCATTER) {
            const int d0 = (n % C_) % D_;
#pragma unroll
            for (int mi = 0; mi < 2; mi++) {
                const int m = row0 + wr*32 + mi*16 + (lane >> 2);
                const int b = m / T_, t = m % T_;
                const size_t bse = (((size_t)(b*H_ + hh)) * T_ + t) * D_ + d0;
                const float v0 = acc[mi][ni][0] + b0, v1 = acc[mi][ni][1] + b1;
                const float v2 = acc[mi][ni][2] + b0, v3 = acc[mi][ni][3] + b1;
                if (which == 0) {
                    store_split2h(&g_qh[bse], &g_ql[bse], v0 * QSCALE, v1 * QSCALE);
                    store_split2h(&g_qh[bse + 8*D_], &g_ql[bse + 8*D_],
                                  v2 * QSCALE, v3 * QSCALE);
                } else if (which == 1) {
                    *(uint32_t*)&g_k[bse]        = pack_h2(v0, v1);
                    *(uint32_t*)&g_k[bse + 8*D_] = pack_h2(v2, v3);
                } else {
                    *(uint32_t*)&g_v[bse]        = pack_h2(v0, v1);
                    *(uint32_t*)&g_v[bse + 8*D_] = pack_h2(v2, v3);
                }
            }
        } else {
#pragma unroll
            for (int mi = 0; mi < 2; mi++) {
                const int m = row0 + wr*32 + mi*16 + (lane >> 2);
                *(float2*)&out[(size_t)m * N + n] =
                    make_float2(acc[mi][ni][0] + b0, acc[mi][ni][1] + b1);
                *(float2*)&out[(size_t)(m + 8) * N + n] =
                    make_float2(acc[mi][ni][2] + b0, acc[mi][ni][3] + b1);
            }
        }
    }
}

// ---------------- fp16 flash attention: mbarrier 3-buffer async pipeline --------
#define ATT_PITCH 72
#define KV_ARR (64*ATT_PITCH*2)     /* 9216 B per array */
#define KV_STG (2*KV_ARR)           /* 18432 B per stage: K|V */
#define NBUF 3
#define ATT_SMEM (NBUF*KV_STG)      /* 55296 B */

__global__ __launch_bounds__(256, 2) void attn_mma_kernel()
{
    extern __shared__ char dsm[];
    __shared__ __align__(8) unsigned long long s_mb[2*NBUF];
    const uint32_t base = s2u(dsm);
    const uint32_t mbF = s2u(&s_mb[0]);      // full[0..2]
    const uint32_t mbE = s2u(&s_mb[NBUF]);   // free[0..2]
    __half* smp = (__half*)dsm;

    const int b = blockIdx.z, h = blockIdx.y;
    const int qt = gridDim.x - 1 - blockIdx.x;   // longest-first
    const int q0 = qt * 128;
    const int tid = threadIdx.x, lane = tid & 31, wid = tid >> 5;
    const size_t hb = ((size_t)(b*H_ + h)) * T_ * D_;

    if (tid == 0) {
#pragma unroll
        for (int i = 0; i < NBUF; i++) {
            MBARRIER_INIT(mbF + i*8, 256);
            MBARRIER_INIT(mbE + i*8, 256);
        }
    }

    // ---- stage Q (128x64 hi/lo) through smem (before any K/V fill), frag load --
    {
        const int row = tid >> 1, cg = (tid & 1) * 32;
        const uint4* s4h = (const uint4*)(g_qh + hb + (size_t)(q0+row)*D_ + cg);
        const uint4* s4l = (const uint4*)(g_ql + hb + (size_t)(q0+row)*D_ + cg);
        uint4* d4h = (uint4*)(smp + row*ATT_PITCH + cg);
        uint4* d4l = (uint4*)(smp + 128*ATT_PITCH + row*ATT_PITCH + cg);
#pragma unroll
        for (int i = 0; i < 4; i++) { d4h[i] = s4h[i]; d4l[i] = s4l[i]; }
    }
    __syncthreads();

    uint32_t qh[4][4], ql[4][4];
    {
        const int qr = lane & 15, qc = (lane & 16) >> 1;
        const uint32_t baseH = base + (uint32_t)((wid*16 + qr)*ATT_PITCH + qc) * 2;
        const uint32_t baseL = baseH + (uint32_t)(128*ATT_PITCH*2);
#pragma unroll
        for (int kk = 0; kk < 4; kk++) {
            LDM_X4(qh[kk], baseH + kk * 32);
            LDM_X4(ql[kk], baseL + kk * 32);
        }
    }
    __syncthreads();   // Q reads done + mbarriers visible before fills

    float o[8][4];
#pragma unroll
    for (int n = 0; n < 8; n++)
#pragma unroll
        for (int r = 0; r < 4; r++) o[n][r] = 0.f;
    float m0 = -1e30f, m1 = -1e30f, l0 = 0.f, l1 = 0.f;

    const int kbrow = (lane & 7) + ((lane & 16) >> 1);
    const int kbcol = (lane & 8);
    const int vrow  = lane & 15;
    const int vcolg = (lane & 16) >> 1;
    const uint32_t kOff = (uint32_t)(kbrow*ATT_PITCH + kbcol) * 2;
    const uint32_t vOff = KV_ARR + (uint32_t)(vrow*ATT_PITCH + vcolg) * 2;

    const int kvr = tid >> 3, kvc = (tid & 7) * 8;
    const uint32_t dOff = (uint32_t)(kvr*ATT_PITCH + kvc) * 2;
    const uint32_t rstep = 32*ATT_PITCH*2;

    auto fill = [&](int k0, int buf) {
        const uint32_t sb = base + buf * KV_STG;
        const size_t g = hb + (size_t)(k0 + kvr)*D_ + kvc;
        cpa16(sb + dOff,                  g_k + g);
        cpa16(sb + dOff + rstep,          g_k + g + 32*D_);
        cpa16(sb + KV_ARR + dOff,         g_v + g);
        cpa16(sb + KV_ARR + dOff + rstep, g_v + g + 32*D_);
    };

    const int row_lo = q0 + wid*16 + (lane >> 2);
    const int row_hi_warp = q0 + wid*16 + 15;
    const int ntiles = q0/64 + 2;

    // prologue: fill up to NBUF tiles
    const int pre = (ntiles < NBUF) ? ntiles : NBUF;
    for (int t = 0; t < pre; t++) {
        fill(t * 64, t);
        CPASYNC_MBAR_ARRIVE(mbF + t*8);
    }

#pragma unroll 1
    for (int t = 0; t < ntiles; t++) {
        const int k0 = t * 64;
        const int bu = t % NBUF;
        const int u  = t / NBUF;
        const uint32_t sb = base + bu * KV_STG;

        MBARRIER_WAIT_PARITY(mbF + bu*8, u & 1);

        if (k0 <= row_hi_warp) {

        float s[8][4];
#pragma unroll
        for (int n = 0; n < 8; n++)
#pragma unroll
            for (int r = 0; r < 4; r++) s[n][r] = 0.f;

#pragma unroll
        for (int kk = 0; kk < 4; kk++) {
            uint32_t kf[4][4];
#pragma unroll
            for (int np = 0; np < 4; np++)
                LDM_X4(kf[np], sb + kOff + (uint32_t)(np*16*ATT_PITCH)*2 + kk*32);
#pragma unroll
            for (int np = 0; np < 4; np++) {
                MMA16816(s[2*np],   qh[kk], kf[np]);
                MMA16816(s[2*np+1], qh[kk], kf[np]+2);
            }
#pragma unroll
            for (int np = 0; np < 4; np++) {
                MMA16816(s[2*np],   ql[kk], kf[np]);
                MMA16816(s[2*np+1], ql[kk], kf[np]+2);
            }
        }

        if (k0 + 64 > q0) {
#pragma unroll
            for (int n = 0; n < 8; n++) {
                const int c = k0 + n*8 + 2*(lane & 3);
                if (c     > row_lo)     s[n][0] = -1e30f;
                if (c + 1 > row_lo)     s[n][1] = -1e30f;
                if (c     > row_lo + 8) s[n][2] = -1e30f;
                if (c + 1 > row_lo + 8) s[n][3] = -1e30f;
            }
        }

        float tm0 = -1e30f, tm1 = -1e30f;
#pragma unroll
        for (int n = 0; n < 8; n++) {
            tm0 = fmaxf(tm0, fmaxf(s[n][0], s[n][1]));
            tm1 = fmaxf(tm1, fmaxf(s[n][2], s[n][3]));
        }
        tm0 = fmaxf(tm0, __shfl_xor_sync(0xffffffff, tm0, 1));
        tm0 = fmaxf(tm0, __shfl_xor_sync(0xffffffff, tm0, 2));
        tm1 = fmaxf(tm1, __shfl_xor_sync(0xffffffff, tm1, 1));
        tm1 = fmaxf(tm1, __shfl_xor_sync(0xffffffff, tm1, 2));

        const float mn0 = fmaxf(m0, tm0), mn1 = fmaxf(m1, tm1);
        const float c0 = ex2f(m0 - mn0), c1 = ex2f(m1 - mn1);
        m0 = mn0; m1 = mn1;
#pragma unroll
        for (int n = 0; n < 8; n++) {
            o[n][0] *= c0; o[n][1] *= c0; o[n][2] *= c1; o[n][3] *= c1;
        }

        float ls0 = 0.f, ls1 = 0.f;
#pragma unroll
        for (int n = 0; n < 8; n++) {
            s[n][0] = ex2f(s[n][0] - m0);
            s[n][1] = ex2f(s[n][1] - m0);
            s[n][2] = ex2f(s[n][2] - m1);
            s[n][3] = ex2f(s[n][3] - m1);
            ls0 += s[n][0] + s[n][1];
            ls1 += s[n][2] + s[n][3];
        }
        ls0 += __shfl_xor_sync(0xffffffff, ls0, 1);
        ls0 += __shfl_xor_sync(0xffffffff, ls0, 2);
        ls1 += __shfl_xor_sync(0xffffffff, ls1, 1);
        ls1 += __shfl_xor_sync(0xffffffff, ls1, 2);
        l0 = l0 * c0 + ls0;
        l1 = l1 * c1 + ls1;

        uint32_t pah[4][4];
#pragma unroll
        for (int j = 0; j < 4; j++) {
            pah[j][0] = pack_h2(s[2*j][0],   s[2*j][1]);
            pah[j][1] = pack_h2(s[2*j][2],   s[2*j][3]);
            pah[j][2] = pack_h2(s[2*j+1][0], s[2*j+1][1]);
            pah[j][3] = pack_h2(s[2*j+1][2], s[2*j+1][3]);
        }

#pragma unroll
        for (int kk = 0; kk < 4; kk++) {
            uint32_t vf[4][4];
#pragma unroll
            for (int nc = 0; nc < 4; nc++)
                LDM_X4T(vf[nc], sb + vOff + (uint32_t)(kk*16*ATT_PITCH)*2 + nc*32);
#pragma unroll
            for (int nc = 0; nc < 4; nc++) {
                MMA16816(o[2*nc],   pah[kk], vf[nc]);
                MMA16816(o[2*nc+1], pah[kk], vf[nc]+2);
            }
        }

        } // end skip-fully-masked

        // signal this buffer consumed (all threads, even skipped warps)
        MBARRIER_ARRIVE(mbE + bu*8);

        // refill this buffer for tile t+NBUF once every warp is done with it
        if (t + NBUF < ntiles) {
            MBARRIER_WAIT_PARITY(mbE + bu*8, u & 1);
            fill((t + NBUF) * 64, bu);
            CPASYNC_MBAR_ARRIVE(mbF + bu*8);
        }
    }

    // ---- epilogue: y hi-only ----
    const float inv0 = 1.f / l0, inv1 = 1.f / l1;
    const int r0 = row_lo, r1 = row_lo + 8;
#pragma unroll
    for (int n = 0; n < 8; n++) {
        const int d = n*8 + 2*(lane & 3);
        const size_t y0 = ((size_t)(b*T_ + r0))*C_ + h*D_ + d;
        const size_t y1 = ((size_t)(b*T_ + r1))*C_ + h*D_ + d;
        *(uint32_t*)&g_yh[y0] = pack_h2(o[n][0]*inv0, o[n][1]*inv0);
        *(uint32_t*)&g_yh[y1] = pack_h2(o[n][2]*inv1, o[n][3]*inv1);
    }
}

// -------------------------------------------------------------------------------
extern "C" void kernel_launch(void* const* d_in, const int* in_sizes, int n_in,
                              void* d_out, int out_size)
{
    const float* x      = (const float*)d_in[0];
    const float* w_attn = (const float*)d_in[1];
    const float* b_attn = (const float*)d_in[2];
    const float* w_proj = (const float*)d_in[3];
    const float* b_proj = (const float*)d_in[4];
    float* out = (float*)d_out;

    cudaFuncSetAttribute(gemm_fp16<true, 2>,
        cudaFuncAttributeMaxDynamicSharedMemorySize, GEMM_SMEM);
    cudaFuncSetAttribute(gemm_fp16<false, 1>,
        cudaFuncAttributeMaxDynamicSharedMemorySize, GEMM_SMEM);
    cudaFuncSetAttribute(attn_mma_kernel,
        cudaFuncAttributeMaxDynamicSharedMemorySize, ATT_SMEM);

    {
        int total = NX + NWA + NWP;
        preprocess_kernel<<<(total + 255) / 256, 256>>>(x, w_attn, w_proj);
    }

    dim3 g1(3 * C_ / BN, M_ / BM);   // (24, 64)
    gemm_fp16<true, 2><<<g1, 256, GEMM_SMEM>>>(b_attn, nullptr, 3 * C_);

    dim3 g2(T_ / 128, H_, B_);       // (16, 16, 4)
    attn_mma_kernel<<<g2, 256, ATT_SMEM>>>();

    dim3 g3(C_ / BN, M_ / BM);       // (8, 64)
    gemm_fp16<false, 1><<<g3, 256, GEMM_SMEM>>>(b_proj, out, C_);
}

// round 13
// speedup vs baseline: 1.0942x; 1.0942x over previous
#include <cuda_runtime.h>
#include <cuda_fp16.h>
#include <cstdint>

#define B_ 4
#define T_ 2048
#define C_ 1024
#define H_ 16
#define D_ 64
#define M_ (B_*T_)   /* 8192 */

// ---------------- device scratch (fp16) ----------------------------------------
__device__ __half g_xh[(size_t)M_*C_];
__device__ __half g_xl[(size_t)M_*C_];
__device__ __half g_wa[(size_t)C_*3*C_];
__device__ __half g_wp[(size_t)C_*C_];
__device__ __half g_yh[(size_t)M_*C_];
__device__ __half g_qh[(size_t)M_*C_];
__device__ __half g_ql[(size_t)M_*C_];
__device__ __half g_k[(size_t)M_*C_];
__device__ __half g_v[(size_t)M_*C_];

// ---------------- helpers ------------------------------------------------------
__device__ __forceinline__ uint32_t s2u(const void* p) {
    return (uint32_t)__cvta_generic_to_shared(p);
}
__device__ __forceinline__ void cpa16(uint32_t dst, const void* src) {
    asm volatile("cp.async.cg.shared.global [%0], [%1], 16;" :: "r"(dst), "l"(src));
}
#define CP_COMMIT() asm volatile("cp.async.commit_group;" ::: "memory")
#define CP_WAIT0()  asm volatile("cp.async.wait_group 0;" ::: "memory")
#define CP_WAIT2()  asm volatile("cp.async.wait_group 2;" ::: "memory")

#define LDM_X4(r, addr) \
    asm volatile("ldmatrix.sync.aligned.m8n8.x4.shared.b16 {%0,%1,%2,%3},[%4];" \
        : "=r"((r)[0]), "=r"((r)[1]), "=r"((r)[2]), "=r"((r)[3]) : "r"(addr))
#define LDM_X4T(r, addr) \
    asm volatile("ldmatrix.sync.aligned.m8n8.x4.trans.shared.b16 {%0,%1,%2,%3},[%4];" \
        : "=r"((r)[0]), "=r"((r)[1]), "=r"((r)[2]), "=r"((r)[3]) : "r"(addr))

#define MMA16816(d, a, b) \
    asm volatile("mma.sync.aligned.m16n8k16.row.col.f32.f16.f16.f32 " \
        "{%0,%1,%2,%3},{%4,%5,%6,%7},{%8,%9},{%0,%1,%2,%3};" \
        : "+f"((d)[0]), "+f"((d)[1]), "+f"((d)[2]), "+f"((d)[3]) \
        : "r"((a)[0]), "r"((a)[1]), "r"((a)[2]), "r"((a)[3]), \
          "r"((b)[0]), "r"((b)[1]))

__device__ __forceinline__ float ex2f(float x) {
    float y;
    asm("ex2.approx.f32 %0, %1;" : "=f"(y) : "f"(x));
    return y;
}

__device__ __forceinline__ uint32_t pack_h2(float a, float b) {
    __half2 v = __floats2half2_rn(a, b);
    return *(uint32_t*)&v;
}
__device__ __forceinline__ uint32_t pack_h2_lo(float a, float b, uint32_t hibits) {
    __half2 h = *(__half2*)&hibits;
    __half2 v;
    v.x = __float2half_rn(a - __half2float(h.x));
    v.y = __float2half_rn(b - __half2float(h.y));
    return *(uint32_t*)&v;
}
__device__ __forceinline__ void store_split2h(
    __half* ph, __half* pl, float a, float b)
{
    uint32_t hi = pack_h2(a, b);
    uint32_t lo = pack_h2_lo(a, b, hi);
    *(uint32_t*)ph = hi;
    *(uint32_t*)pl = lo;
}

// q pre-scale: 1/sqrt(D) * log2(e)
#define QSCALE 0.1803368801111306f

// ---------------- merged preprocessing ------------------------------------------
#define NX  (M_*C_/4)
#define NWA (3*C_*C_/4)
#define NWP (C_*C_/4)

__global__ void preprocess_kernel(const float* __restrict__ x,
                                  const float* __restrict__ wa,
                                  const float* __restrict__ wp)
{
    int i = blockIdx.x * blockDim.x + threadIdx.x;
    if (i < NX) {
        float4 v = ((const float4*)x)[i];
        uint32_t h0 = pack_h2(v.x, v.y), h1 = pack_h2(v.z, v.w);
        uint32_t l0 = pack_h2_lo(v.x, v.y, h0), l1 = pack_h2_lo(v.z, v.w, h1);
        ((uint2*)g_xh)[i] = make_uint2(h0, h1);
        ((uint2*)g_xl)[i] = make_uint2(l0, l1);
    } else if (i < NX + NWA) {
        int j = i - NX;
        float4 v = ((const float4*)wa)[j];
        ((uint2*)g_wa)[j] = make_uint2(pack_h2(v.x, v.y), pack_h2(v.z, v.w));
    } else if (i < NX + NWA + NWP) {
        int j = i - NX - NWA;
        float4 v = ((const float4*)wp)[j];
        ((uint2*)g_wp)[j] = make_uint2(pack_h2(v.x, v.y), pack_h2(v.z, v.w));
    }
}

// ---------------- fp16 GEMM, BK=16, 4-stage (R10-measured pipeline) -------------
// MODE 0: proj (A=y single, B=wp, out fp32)
// MODE 1: qkv Q/K cols (A=x split 2-product, B=wa cols [0,2C))
// MODE 2: qkv V cols  (A=x single 1-product, B=wa cols [2C,3C))
#define BM 128
#define BN 128
#define BK 16
#define AST 24
#define BST 136
#define KTILES (C_/BK)          /* 64 */
#define STAGES 4
#define ASZ (BM*AST*2)
#define BSZ (BK*BST*2)
#define STG (2*ASZ + BSZ)
#define GEMM_SMEM (STAGES*STG)  /* 66560 B */

template<int MODE, int NPROD>
__global__ __launch_bounds__(256, 2) void gemm_fp16(
    const float* __restrict__ bias, float* __restrict__ out)
{
    extern __shared__ char dsm[];
    const uint32_t base = s2u(dsm);

    const __half* Agh = (MODE == 0) ? g_yh : g_xh;
    const __half* Agl = (MODE == 0) ? g_yh : g_xl;   // unused when NPROD==1
    const __half* Bg  = (MODE == 0) ? g_wp : (g_wa + ((MODE == 2) ? 2*C_ : 0));
    const int NSTR = (MODE == 0) ? C_ : 3*C_;        // B row stride

    const int K = C_;
    const int tid  = threadIdx.x;
    const int lane = tid & 31, wid = tid >> 5;
    const int wr = wid >> 1, wc = wid & 1;           // 4x2 warp grid
    const int row0 = blockIdx.y * BM, col0 = blockIdx.x * BN;

    const int rA = tid >> 1, cA = tid & 1;
    const int rB = tid >> 4, cB = tid & 15;

    const __half* srcAh = Agh + (size_t)(row0 + rA) * K + cA * 8;
    const __half* srcAl = Agl + (size_t)(row0 + rA) * K + cA * 8;
    const __half* srcB  = Bg  + (size_t)rB * NSTR + col0 + cB * 8;

    const uint32_t offA = (uint32_t)(rA*AST + cA*8) * 2;
    const uint32_t offB = (uint32_t)(rB*BST + cB*8) * 2;

    auto load_stage = [&](int kt, int buf) {
        const uint32_t sb = base + buf * STG;
        cpa16(sb + offA, srcAh + kt * BK);
        if (NPROD == 2)
            cpa16(sb + ASZ + offA, srcAl + kt * BK);
        cpa16(sb + 2*ASZ + offB, srcB + (size_t)kt * BK * NSTR);
    };

    const int lm = lane & 15, lh = lane >> 4;
    const uint32_t aOff = (uint32_t)((wr*32 + lm) * AST + lh * 8) * 2;
    const uint32_t bOff = (uint32_t)(lm * BST + (wc*64 + lh*8)) * 2;

    float acc[2][8][4];
#pragma unroll
    for (int mi = 0; mi < 2; mi++)
#pragma unroll
        for (int ni = 0; ni < 8; ni++)
#pragma unroll
            for (int r = 0; r < 4; r++) acc[mi][ni][r] = 0.f;

    auto compute = [&](int buf) {
        const uint32_t sb = base + buf * STG;
        const uint32_t aH = sb + aOff;
        const uint32_t aL = sb + ASZ + aOff;
        const uint32_t bB = sb + 2*ASZ + bOff;
        uint32_t ah[2][4], al[2][4], bb[8][2], r[4];
#pragma unroll
        for (int mi = 0; mi < 2; mi++) LDM_X4(ah[mi], aH + mi * (16*AST*2));
#pragma unroll
        for (int g = 0; g < 4; g++) {
            LDM_X4T(r, bB + g * 32);
            bb[2*g][0]   = r[0]; bb[2*g][1]   = r[1];
            bb[2*g+1][0] = r[2]; bb[2*g+1][1] = r[3];
        }
#pragma unroll
        for (int mi = 0; mi < 2; mi++)
#pragma unroll
            for (int ni = 0; ni < 8; ni++) MMA16816(acc[mi][ni], ah[mi], bb[ni]);
        if (NPROD == 2) {
#pragma unroll
            for (int mi = 0; mi < 2; mi++) LDM_X4(al[mi], aL + mi * (16*AST*2));
#pragma unroll
            for (int mi = 0; mi < 2; mi++)
#pragma unroll
                for (int ni = 0; ni < 8; ni++) MMA16816(acc[mi][ni], al[mi], bb[ni]);
        }
    };

#pragma unroll
    for (int s = 0; s < STAGES - 1; s++) {
        load_stage(s, s);
        CP_COMMIT();
    }

#pragma unroll 1
    for (int kt = 0; kt < KTILES; kt++) {
        CP_WAIT2();
        __syncthreads();
        if (kt + STAGES - 1 < KTILES)
            load_stage(kt + STAGES - 1, (kt + STAGES - 1) & (STAGES - 1));
        CP_COMMIT();
        compute(kt & (STAGES - 1));
    }

    // ---------------- epilogue ----------------
    const int ncol0 = col0 + wc * 64;

#pragma unroll
    for (int ni = 0; ni < 8; ni++) {
        const int n = ncol0 + ni*8 + (lane & 3) * 2;      // local col
        const float b0 = bias[n], b1 = bias[n + 1];
        if (MODE == 0) {
#pragma unroll
            for (int mi = 0; mi < 2; mi++) {
                const int m = row0 + wr*32 + mi*16 + (lane >> 2);
                *(float2*)&out[(size_t)m * C_ + n] =
                    make_float2(acc[mi][ni][0] + b0, acc[mi][ni][1] + b1);
                *(float2*)&out[(size_t)(m + 8) * C_ + n] =
                    make_float2(acc[mi][ni][2] + b0, acc[mi][ni][3] + b1);
            }
        } else {
            const int which = (MODE == 1) ? (n / C_) : 2; // 0=q,1=k,2=v
            const int c0 = n % C_;
            const int hh = c0 / D_, d0 = c0 % D_;
#pragma unroll
            for (int mi = 0; mi < 2; mi++) {
                const int m = row0 + wr*32 + mi*16 + (lane >> 2);
                const int b = m / T_, t = m % T_;
                const size_t bse = (((size_t)(b*H_ + hh)) * T_ + t) * D_ + d0;
                const float v0 = acc[mi][ni][0] + b0, v1 = acc[mi][ni][1] + b1;
                const float v2 = acc[mi][ni][2] + b0, v3 = acc[mi][ni][3] + b1;
                if (which == 0) {
                    store_split2h(&g_qh[bse], &g_ql[bse], v0 * QSCALE, v1 * QSCALE);
                    store_split2h(&g_qh[bse + 8*D_], &g_ql[bse + 8*D_],
                                  v2 * QSCALE, v3 * QSCALE);
                } else if (which == 1) {
                    *(uint32_t*)&g_k[bse]        = pack_h2(v0, v1);
                    *(uint32_t*)&g_k[bse + 8*D_] = pack_h2(v2, v3);
                } else {
                    *(uint32_t*)&g_v[bse]        = pack_h2(v0, v1);
                    *(uint32_t*)&g_v[bse + 8*D_] = pack_h2(v2, v3);
                }
            }
        }
    }
}

// ---------------- fp16 flash attention (R10-measured: dbuf + syncthreads) -------
#define ATT_PITCH 72
#define KV_ARR (64*ATT_PITCH*2)
#define KV_STG (2*KV_ARR)
#define ATT_SMEM (2*KV_STG)

__global__ __launch_bounds__(256, 2) void attn_mma_kernel()
{
    extern __shared__ char dsm[];
    const uint32_t base = s2u(dsm);
    __half* smp = (__half*)dsm;

    const int b = blockIdx.z, h = blockIdx.y;
    const int qt = gridDim.x - 1 - blockIdx.x;   // longest-first
    const int q0 = qt * 128;
    const int tid = threadIdx.x, lane = tid & 31, wid = tid >> 5;
    const size_t hb = ((size_t)(b*H_ + h)) * T_ * D_;

    {
        const int row = tid >> 1, cg = (tid & 1) * 32;
        const uint4* s4h = (const uint4*)(g_qh + hb + (size_t)(q0+row)*D_ + cg);
        const uint4* s4l = (const uint4*)(g_ql + hb + (size_t)(q0+row)*D_ + cg);
        uint4* d4h = (uint4*)(smp + row*ATT_PITCH + cg);
        uint4* d4l = (uint4*)(smp + 128*ATT_PITCH + row*ATT_PITCH + cg);
#pragma unroll
        for (int i = 0; i < 4; i++) { d4h[i] = s4h[i]; d4l[i] = s4l[i]; }
    }
    __syncthreads();

    uint32_t qh[4][4], ql[4][4];
    {
        const int qr = lane & 15, qc = (lane & 16) >> 1;
        const uint32_t baseH = base + (uint32_t)((wid*16 + qr)*ATT_PITCH + qc) * 2;
        const uint32_t baseL = baseH + (uint32_t)(128*ATT_PITCH*2);
#pragma unroll
        for (int kk = 0; kk < 4; kk++) {
            LDM_X4(qh[kk], baseH + kk * 32);
            LDM_X4(ql[kk], baseL + kk * 32);
        }
    }
    __syncthreads();

    float o[8][4];
#pragma unroll
    for (int n = 0; n < 8; n++)
#pragma unroll
        for (int r = 0; r < 4; r++) o[n][r] = 0.f;
    float m0 = -1e30f, m1 = -1e30f, l0 = 0.f, l1 = 0.f;

    const int kbrow = (lane & 7) + ((lane & 16) >> 1);
    const int kbcol = (lane & 8);
    const int vrow  = lane & 15;
    const int vcolg = (lane & 16) >> 1;
    const uint32_t kOff = (uint32_t)(kbrow*ATT_PITCH + kbcol) * 2;
    const uint32_t vOff = KV_ARR + (uint32_t)(vrow*ATT_PITCH + vcolg) * 2;

    const int kvr = tid >> 3, kvc = (tid & 7) * 8;
    const uint32_t dOff = (uint32_t)(kvr*ATT_PITCH + kvc) * 2;
    const uint32_t rstep = 32*ATT_PITCH*2;

    auto load_tile = [&](int k0, int buf) {
        const uint32_t sb = base + buf * KV_STG;
        const size_t g = hb + (size_t)(k0 + kvr)*D_ + kvc;
        cpa16(sb + dOff,                  g_k + g);
        cpa16(sb + dOff + rstep,          g_k + g + 32*D_);
        cpa16(sb + KV_ARR + dOff,         g_v + g);
        cpa16(sb + KV_ARR + dOff + rstep, g_v + g + 32*D_);
    };

    const int row_lo = q0 + wid*16 + (lane >> 2);
    const int row_hi_warp = q0 + wid*16 + 15;
    const int ntiles = q0/64 + 2;

    load_tile(0, 0);
    CP_COMMIT();

#pragma unroll 1
    for (int t = 0; t < ntiles; t++) {
        const int k0 = t * 64;
        const uint32_t sb = base + (t & 1) * KV_STG;

        CP_WAIT0();
        __syncthreads();
        if (t + 1 < ntiles) {
            load_tile(k0 + 64, (t + 1) & 1);
            CP_COMMIT();
        }

        if (k0 <= row_hi_warp) {

        float s[8][4];
#pragma unroll
        for (int n = 0; n < 8; n++)
#pragma unroll
            for (int r = 0; r < 4; r++) s[n][r] = 0.f;

#pragma unroll
        for (int kk = 0; kk < 4; kk++) {
            uint32_t kf[4][4];
#pragma unroll
            for (int np = 0; np < 4; np++)
                LDM_X4(kf[np], sb + kOff + (uint32_t)(np*16*ATT_PITCH)*2 + kk*32);
#pragma unroll
            for (int np = 0; np < 4; np++) {
                MMA16816(s[2*np],   qh[kk], kf[np]);
                MMA16816(s[2*np+1], qh[kk], kf[np]+2);
            }
#pragma unroll
            for (int np = 0; np < 4; np++) {
                MMA16816(s[2*np],   ql[kk], kf[np]);
                MMA16816(s[2*np+1], ql[kk], kf[np]+2);
            }
        }

        if (k0 + 64 > q0) {
#pragma unroll
            for (int n = 0; n < 8; n++) {
                const int c = k0 + n*8 + 2*(lane & 3);
                if (c     > row_lo)     s[n][0] = -1e30f;
                if (c + 1 > row_lo)     s[n][1] = -1e30f;
                if (c     > row_lo + 8) s[n][2] = -1e30f;
                if (c + 1 > row_lo + 8) s[n][3] = -1e30f;
            }
        }

        float tm0 = -1e30f, tm1 = -1e30f;
#pragma unroll
        for (int n = 0; n < 8; n++) {
            tm0 = fmaxf(tm0, fmaxf(s[n][0], s[n][1]));
            tm1 = fmaxf(tm1, fmaxf(s[n][2], s[n][3]));
        }
        tm0 = fmaxf(tm0, __shfl_xor_sync(0xffffffff, tm0, 1));
        tm0 = fmaxf(tm0, __shfl_xor_sync(0xffffffff, tm0, 2));
        tm1 = fmaxf(tm1, __shfl_xor_sync(0xffffffff, tm1, 1));
        tm1 = fmaxf(tm1, __shfl_xor_sync(0xffffffff, tm1, 2));

        const float mn0 = fmaxf(m0, tm0), mn1 = fmaxf(m1, tm1);
        const float c0 = ex2f(m0 - mn0), c1 = ex2f(m1 - mn1);
        m0 = mn0; m1 = mn1;
#pragma unroll
        for (int n = 0; n < 8; n++) {
            o[n][0] *= c0; o[n][1] *= c0; o[n][2] *= c1; o[n][3] *= c1;
        }

        float ls0 = 0.f, ls1 = 0.f;
#pragma unroll
        for (int n = 0; n < 8; n++) {
            s[n][0] = ex2f(s[n][0] - m0);
            s[n][1] = ex2f(s[n][1] - m0);
            s[n][2] = ex2f(s[n][2] - m1);
            s[n][3] = ex2f(s[n][3] - m1);
            ls0 += s[n][0] + s[n][1];
            ls1 += s[n][2] + s[n][3];
        }
        ls0 += __shfl_xor_sync(0xffffffff, ls0, 1);
        ls0 += __shfl_xor_sync(0xffffffff, ls0, 2);
        ls1 += __shfl_xor_sync(0xffffffff, ls1, 1);
        ls1 += __shfl_xor_sync(0xffffffff, ls1, 2);
        l0 = l0 * c0 + ls0;
        l1 = l1 * c1 + ls1;

        uint32_t pah[4][4];
#pragma unroll
        for (int j = 0; j < 4; j++) {
            pah[j][0] = pack_h2(s[2*j][0],   s[2*j][1]);
            pah[j][1] = pack_h2(s[2*j][2],   s[2*j][3]);
            pah[j][2] = pack_h2(s[2*j+1][0], s[2*j+1][1]);
            pah[j][3] = pack_h2(s[2*j+1][2], s[2*j+1][3]);
        }

#pragma unroll
        for (int kk = 0; kk < 4; kk++) {
            uint32_t vf[4][4];
#pragma unroll
            for (int nc = 0; nc < 4; nc++)
                LDM_X4T(vf[nc], sb + vOff + (uint32_t)(kk*16*ATT_PITCH)*2 + nc*32);
#pragma unroll
            for (int nc = 0; nc < 4; nc++) {
                MMA16816(o[2*nc],   pah[kk], vf[nc]);
                MMA16816(o[2*nc+1], pah[kk], vf[nc]+2);
            }
        }

        }
    }

    const float inv0 = 1.f / l0, inv1 = 1.f / l1;
    const int r0 = row_lo, r1 = row_lo + 8;
#pragma unroll
    for (int n = 0; n < 8; n++) {
        const int d = n*8 + 2*(lane & 3);
        const size_t y0 = ((size_t)(b*T_ + r0))*C_ + h*D_ + d;
        const size_t y1 = ((size_t)(b*T_ + r1))*C_ + h*D_ + d;
        *(uint32_t*)&g_yh[y0] = pack_h2(o[n][0]*inv0, o[n][1]*inv0);
        *(uint32_t*)&g_yh[y1] = pack_h2(o[n][2]*inv1, o[n][3]*inv1);
    }
}

// -------------------------------------------------------------------------------
extern "C" void kernel_launch(void* const* d_in, const int* in_sizes, int n_in,
                              void* d_out, int out_size)
{
    const float* x      = (const float*)d_in[0];
    const float* w_attn = (const float*)d_in[1];
    const float* b_attn = (const float*)d_in[2];
    const float* w_proj = (const float*)d_in[3];
    const float* b_proj = (const float*)d_in[4];
    float* out = (float*)d_out;

    cudaFuncSetAttribute(gemm_fp16<1, 2>,
        cudaFuncAttributeMaxDynamicSharedMemorySize, GEMM_SMEM);
    cudaFuncSetAttribute(gemm_fp16<2, 1>,
        cudaFuncAttributeMaxDynamicSharedMemorySize, GEMM_SMEM);
    cudaFuncSetAttribute(gemm_fp16<0, 1>,
        cudaFuncAttributeMaxDynamicSharedMemorySize, GEMM_SMEM);
    cudaFuncSetAttribute(attn_mma_kernel,
        cudaFuncAttributeMaxDynamicSharedMemorySize, ATT_SMEM);

    {
        int total = NX + NWA + NWP;
        preprocess_kernel<<<(total + 255) / 256, 256>>>(x, w_attn, w_proj);
    }

    // Q/K columns: 2-product
    dim3 gqk(2 * C_ / BN, M_ / BM);   // (16, 64)
    gemm_fp16<1, 2><<<gqk, 256, GEMM_SMEM>>>(b_attn, nullptr);

    // V columns: 1-product (bias pointer pre-offset to V range)
    dim3 gv(C_ / BN, M_ / BM);        // (8, 64)
    gemm_fp16<2, 1><<<gv, 256, GEMM_SMEM>>>(b_attn + 2 * C_, nullptr);

    dim3 g2(T_ / 128, H_, B_);        // (16, 16, 4)
    attn_mma_kernel<<<g2, 256, ATT_SMEM>>>();

    dim3 g3(C_ / BN, M_ / BM);        // (8, 64)
    gemm_fp16<0, 1><<<g3, 256, GEMM_SMEM>>>(b_proj, out);
}

// round 14
// speedup vs baseline: 1.4778x; 1.3506x over previous
#include <cuda_runtime.h>
#include <cuda_fp16.h>
#include <cstdint>

#define B_ 4
#define T_ 2048
#define C_ 1024
#define H_ 16
#define D_ 64
#define M_ (B_*T_)   /* 8192 */

// ---------------- device scratch (fp16) ----------------------------------------
__device__ __half g_x[(size_t)M_*C_];
__device__ __half g_wa[(size_t)C_*3*C_];
__device__ __half g_wp[(size_t)C_*C_];
__device__ __half g_yh[(size_t)M_*C_];
__device__ __half g_q[(size_t)M_*C_];
__device__ __half g_k[(size_t)M_*C_];
__device__ __half g_v[(size_t)M_*C_];

// ---------------- helpers ------------------------------------------------------
__device__ __forceinline__ uint32_t s2u(const void* p) {
    return (uint32_t)__cvta_generic_to_shared(p);
}
__device__ __forceinline__ void cpa16(uint32_t dst, const void* src) {
    asm volatile("cp.async.cg.shared.global [%0], [%1], 16;" :: "r"(dst), "l"(src));
}
#define CP_COMMIT() asm volatile("cp.async.commit_group;" ::: "memory")
#define CP_WAIT0()  asm volatile("cp.async.wait_group 0;" ::: "memory")
#define CP_WAIT2()  asm volatile("cp.async.wait_group 2;" ::: "memory")

#define LDM_X4(r, addr) \
    asm volatile("ldmatrix.sync.aligned.m8n8.x4.shared.b16 {%0,%1,%2,%3},[%4];" \
        : "=r"((r)[0]), "=r"((r)[1]), "=r"((r)[2]), "=r"((r)[3]) : "r"(addr))
#define LDM_X4T(r, addr) \
    asm volatile("ldmatrix.sync.aligned.m8n8.x4.trans.shared.b16 {%0,%1,%2,%3},[%4];" \
        : "=r"((r)[0]), "=r"((r)[1]), "=r"((r)[2]), "=r"((r)[3]) : "r"(addr))

#define MMA16816(d, a, b) \
    asm volatile("mma.sync.aligned.m16n8k16.row.col.f32.f16.f16.f32 " \
        "{%0,%1,%2,%3},{%4,%5,%6,%7},{%8,%9},{%0,%1,%2,%3};" \
        : "+f"((d)[0]), "+f"((d)[1]), "+f"((d)[2]), "+f"((d)[3]) \
        : "r"((a)[0]), "r"((a)[1]), "r"((a)[2]), "r"((a)[3]), \
          "r"((b)[0]), "r"((b)[1]))

__device__ __forceinline__ float ex2f(float x) {
    float y;
    asm("ex2.approx.f32 %0, %1;" : "=f"(y) : "f"(x));
    return y;
}

__device__ __forceinline__ uint32_t pack_h2(float a, float b) {
    __half2 v = __floats2half2_rn(a, b);
    return *(uint32_t*)&v;
}

// q pre-scale: 1/sqrt(D) * log2(e)
#define QSCALE 0.1803368801111306f

// ---------------- merged preprocessing (all single fp16) ------------------------
#define NX  (M_*C_/4)
#define NWA (3*C_*C_/4)
#define NWP (C_*C_/4)

__global__ void preprocess_kernel(const float* __restrict__ x,
                                  const float* __restrict__ wa,
                                  const float* __restrict__ wp)
{
    int i = blockIdx.x * blockDim.x + threadIdx.x;
    if (i < NX) {
        float4 v = ((const float4*)x)[i];
        ((uint2*)g_x)[i] = make_uint2(pack_h2(v.x, v.y), pack_h2(v.z, v.w));
    } else if (i < NX + NWA) {
        int j = i - NX;
        float4 v = ((const float4*)wa)[j];
        ((uint2*)g_wa)[j] = make_uint2(pack_h2(v.x, v.y), pack_h2(v.z, v.w));
    } else if (i < NX + NWA + NWP) {
        int j = i - NX - NWA;
        float4 v = ((const float4*)wp)[j];
        ((uint2*)g_wp)[j] = make_uint2(pack_h2(v.x, v.y), pack_h2(v.z, v.w));
    }
}

// ---------------- fp16 GEMM, 1-product, BK=16, 4-stage --------------------------
// SCATTER: qkv (A=g_x, B=g_wa [1024,3072], scatter q/k/v); else proj.
#define BM 128
#define BN 128
#define BK 16
#define AST 24
#define BST 136
#define KTILES (C_/BK)          /* 64 */
#define STAGES 4
#define ASZ (BM*AST*2)
#define BSZ (BK*BST*2)
#define STG (ASZ + BSZ)         /* 10496 B per stage */
#define GEMM_SMEM (STAGES*STG)  /* 41984 B */

template<bool SCATTER>
__global__ __launch_bounds__(256, 2) void gemm_fp16(
    const float* __restrict__ bias, float* __restrict__ out)
{
    extern __shared__ char dsm[];
    const uint32_t base = s2u(dsm);

    const __half* Ag = SCATTER ? g_x : g_yh;
    const __half* Bg = SCATTER ? g_wa : g_wp;
    const int NSTR = SCATTER ? 3*C_ : C_;

    const int K = C_;
    const int tid  = threadIdx.x;
    const int lane = tid & 31, wid = tid >> 5;
    const int wr = wid >> 1, wc = wid & 1;       // 4x2 warp grid
    const int row0 = blockIdx.y * BM, col0 = blockIdx.x * BN;

    const int rA = tid >> 1, cA = tid & 1;
    const int rB = tid >> 4, cB = tid & 15;

    const __half* srcA = Ag + (size_t)(row0 + rA) * K + cA * 8;
    const __half* srcB = Bg + (size_t)rB * NSTR + col0 + cB * 8;

    const uint32_t offA = (uint32_t)(rA*AST + cA*8) * 2;
    const uint32_t offB = (uint32_t)(rB*BST + cB*8) * 2;

    auto load_stage = [&](int kt, int buf) {
        const uint32_t sb = base + buf * STG;
        cpa16(sb + offA, srcA + kt * BK);
        cpa16(sb + ASZ + offB, srcB + (size_t)kt * BK * NSTR);
    };

    const int lm = lane & 15, lh = lane >> 4;
    const uint32_t aOff = (uint32_t)((wr*32 + lm) * AST + lh * 8) * 2;
    const uint32_t bOff = (uint32_t)(lm * BST + (wc*64 + lh*8)) * 2;

    float acc[2][8][4];
#pragma unroll
    for (int mi = 0; mi < 2; mi++)
#pragma unroll
        for (int ni = 0; ni < 8; ni++)
#pragma unroll
            for (int r = 0; r < 4; r++) acc[mi][ni][r] = 0.f;

    auto compute = [&](int buf) {
        const uint32_t sb = base + buf * STG;
        const uint32_t aA = sb + aOff;
        const uint32_t bB = sb + ASZ + bOff;
        uint32_t aa[2][4], bb[8][2], r[4];
#pragma unroll
        for (int mi = 0; mi < 2; mi++) LDM_X4(aa[mi], aA + mi * (16*AST*2));
#pragma unroll
        for (int g = 0; g < 4; g++) {
            LDM_X4T(r, bB + g * 32);
            bb[2*g][0]   = r[0]; bb[2*g][1]   = r[1];
            bb[2*g+1][0] = r[2]; bb[2*g+1][1] = r[3];
        }
#pragma unroll
        for (int mi = 0; mi < 2; mi++)
#pragma unroll
            for (int ni = 0; ni < 8; ni++) MMA16816(acc[mi][ni], aa[mi], bb[ni]);
    };

#pragma unroll
    for (int s = 0; s < STAGES - 1; s++) {
        load_stage(s, s);
        CP_COMMIT();
    }

#pragma unroll 1
    for (int kt = 0; kt < KTILES; kt++) {
        CP_WAIT2();
        __syncthreads();
        if (kt + STAGES - 1 < KTILES)
            load_stage(kt + STAGES - 1, (kt + STAGES - 1) & (STAGES - 1));
        CP_COMMIT();
        compute(kt & (STAGES - 1));
    }

    // ---------------- epilogue ----------------
    const int ncol0 = col0 + wc * 64;

#pragma unroll
    for (int ni = 0; ni < 8; ni++) {
        const int n = ncol0 + ni*8 + (lane & 3) * 2;
        const float b0 = bias[n], b1 = bias[n + 1];
        if (SCATTER) {
            const int which = n / C_;     // 0=q, 1=k, 2=v
            const int c0 = n % C_;
            const int hh = c0 / D_, d0 = c0 % D_;
            const float sc = (which == 0) ? QSCALE : 1.0f;
            __half* dst = (which == 0) ? g_q : (which == 1) ? g_k : g_v;
#pragma unroll
            for (int mi = 0; mi < 2; mi++) {
                const int m = row0 + wr*32 + mi*16 + (lane >> 2);
                const int b = m / T_, t = m % T_;
                const size_t bse = (((size_t)(b*H_ + hh)) * T_ + t) * D_ + d0;
                *(uint32_t*)&dst[bse] =
                    pack_h2((acc[mi][ni][0] + b0) * sc, (acc[mi][ni][1] + b1) * sc);
                *(uint32_t*)&dst[bse + 8*D_] =
                    pack_h2((acc[mi][ni][2] + b0) * sc, (acc[mi][ni][3] + b1) * sc);
            }
        } else {
#pragma unroll
            for (int mi = 0; mi < 2; mi++) {
                const int m = row0 + wr*32 + mi*16 + (lane >> 2);
                *(float2*)&out[(size_t)m * C_ + n] =
                    make_float2(acc[mi][ni][0] + b0, acc[mi][ni][1] + b1);
                *(float2*)&out[(size_t)(m + 8) * C_ + n] =
                    make_float2(acc[mi][ni][2] + b0, acc[mi][ni][3] + b1);
            }
        }
    }
}

// ---------------- fp16 flash attention: 1-product S, 1-product PV ---------------
#define ATT_PITCH 72
#define KV_ARR (64*ATT_PITCH*2)
#define KV_STG (2*KV_ARR)
#define ATT_SMEM (2*KV_STG)

__global__ __launch_bounds__(256, 2) void attn_mma_kernel()
{
    extern __shared__ char dsm[];
    const uint32_t base = s2u(dsm);
    __half* smp = (__half*)dsm;

    const int b = blockIdx.z, h = blockIdx.y;
    const int qt = gridDim.x - 1 - blockIdx.x;   // longest-first
    const int q0 = qt * 128;
    const int tid = threadIdx.x, lane = tid & 31, wid = tid >> 5;
    const size_t hb = ((size_t)(b*H_ + h)) * T_ * D_;

    // ---- stage Q (128x64 single fp16) through smem, frag load ----
    {
        const int row = tid >> 1, cg = (tid & 1) * 32;
        const uint4* s4 = (const uint4*)(g_q + hb + (size_t)(q0+row)*D_ + cg);
        uint4* d4 = (uint4*)(smp + row*ATT_PITCH + cg);
#pragma unroll
        for (int i = 0; i < 4; i++) d4[i] = s4[i];
    }
    __syncthreads();

    uint32_t qf[4][4];
    {
        const int qr = lane & 15, qc = (lane & 16) >> 1;
        const uint32_t baseQ = base + (uint32_t)((wid*16 + qr)*ATT_PITCH + qc) * 2;
#pragma unroll
        for (int kk = 0; kk < 4; kk++)
            LDM_X4(qf[kk], baseQ + kk * 32);
    }
    __syncthreads();

    float o[8][4];
#pragma unroll
    for (int n = 0; n < 8; n++)
#pragma unroll
        for (int r = 0; r < 4; r++) o[n][r] = 0.f;
    float m0 = -1e30f, m1 = -1e30f, l0 = 0.f, l1 = 0.f;

    const int kbrow = (lane & 7) + ((lane & 16) >> 1);
    const int kbcol = (lane & 8);
    const int vrow  = lane & 15;
    const int vcolg = (lane & 16) >> 1;
    const uint32_t kOff = (uint32_t)(kbrow*ATT_PITCH + kbcol) * 2;
    const uint32_t vOff = KV_ARR + (uint32_t)(vrow*ATT_PITCH + vcolg) * 2;

    const int kvr = tid >> 3, kvc = (tid & 7) * 8;
    const uint32_t dOff = (uint32_t)(kvr*ATT_PITCH + kvc) * 2;
    const uint32_t rstep = 32*ATT_PITCH*2;

    auto load_tile = [&](int k0, int buf) {
        const uint32_t sb = base + buf * KV_STG;
        const size_t g = hb + (size_t)(k0 + kvr)*D_ + kvc;
        cpa16(sb + dOff,                  g_k + g);
        cpa16(sb + dOff + rstep,          g_k + g + 32*D_);
        cpa16(sb + KV_ARR + dOff,         g_v + g);
        cpa16(sb + KV_ARR + dOff + rstep, g_v + g + 32*D_);
    };

    const int row_lo = q0 + wid*16 + (lane >> 2);
    const int row_hi_warp = q0 + wid*16 + 15;
    const int ntiles = q0/64 + 2;

    load_tile(0, 0);
    CP_COMMIT();

#pragma unroll 1
    for (int t = 0; t < ntiles; t++) {
        const int k0 = t * 64;
        const uint32_t sb = base + (t & 1) * KV_STG;

        CP_WAIT0();
        __syncthreads();
        if (t + 1 < ntiles) {
            load_tile(k0 + 64, (t + 1) & 1);
            CP_COMMIT();
        }

        if (k0 <= row_hi_warp) {

        // ---- S = Q K^T (single product) ----
        float s[8][4];
#pragma unroll
        for (int n = 0; n < 8; n++)
#pragma unroll
            for (int r = 0; r < 4; r++) s[n][r] = 0.f;

#pragma unroll
        for (int kk = 0; kk < 4; kk++) {
            uint32_t kf[4][4];
#pragma unroll
            for (int np = 0; np < 4; np++)
                LDM_X4(kf[np], sb + kOff + (uint32_t)(np*16*ATT_PITCH)*2 + kk*32);
#pragma unroll
            for (int np = 0; np < 4; np++) {
                MMA16816(s[2*np],   qf[kk], kf[np]);
                MMA16816(s[2*np+1], qf[kk], kf[np]+2);
            }
        }

        if (k0 + 64 > q0) {
#pragma unroll
            for (int n = 0; n < 8; n++) {
                const int c = k0 + n*8 + 2*(lane & 3);
                if (c     > row_lo)     s[n][0] = -1e30f;
                if (c + 1 > row_lo)     s[n][1] = -1e30f;
                if (c     > row_lo + 8) s[n][2] = -1e30f;
                if (c + 1 > row_lo + 8) s[n][3] = -1e30f;
            }
        }

        float tm0 = -1e30f, tm1 = -1e30f;
#pragma unroll
        for (int n = 0; n < 8; n++) {
            tm0 = fmaxf(tm0, fmaxf(s[n][0], s[n][1]));
            tm1 = fmaxf(tm1, fmaxf(s[n][2], s[n][3]));
        }
        tm0 = fmaxf(tm0, __shfl_xor_sync(0xffffffff, tm0, 1));
        tm0 = fmaxf(tm0, __shfl_xor_sync(0xffffffff, tm0, 2));
        tm1 = fmaxf(tm1, __shfl_xor_sync(0xffffffff, tm1, 1));
        tm1 = fmaxf(tm1, __shfl_xor_sync(0xffffffff, tm1, 2));

        const float mn0 = fmaxf(m0, tm0), mn1 = fmaxf(m1, tm1);
        const float c0 = ex2f(m0 - mn0), c1 = ex2f(m1 - mn1);
        m0 = mn0; m1 = mn1;
#pragma unroll
        for (int n = 0; n < 8; n++) {
            o[n][0] *= c0; o[n][1] *= c0; o[n][2] *= c1; o[n][3] *= c1;
        }

        float ls0 = 0.f, ls1 = 0.f;
#pragma unroll
        for (int n = 0; n < 8; n++) {
            s[n][0] = ex2f(s[n][0] - m0);
            s[n][1] = ex2f(s[n][1] - m0);
            s[n][2] = ex2f(s[n][2] - m1);
            s[n][3] = ex2f(s[n][3] - m1);
            ls0 += s[n][0] + s[n][1];
            ls1 += s[n][2] + s[n][3];
        }
        ls0 += __shfl_xor_sync(0xffffffff, ls0, 1);
        ls0 += __shfl_xor_sync(0xffffffff, ls0, 2);
        ls1 += __shfl_xor_sync(0xffffffff, ls1, 1);
        ls1 += __shfl_xor_sync(0xffffffff, ls1, 2);
        l0 = l0 * c0 + ls0;
        l1 = l1 * c1 + ls1;

        uint32_t pah[4][4];
#pragma unroll
        for (int j = 0; j < 4; j++) {
            pah[j][0] = pack_h2(s[2*j][0],   s[2*j][1]);
            pah[j][1] = pack_h2(s[2*j][2],   s[2*j][3]);
            pah[j][2] = pack_h2(s[2*j+1][0], s[2*j+1][1]);
            pah[j][3] = pack_h2(s[2*j+1][2], s[2*j+1][3]);
        }

#pragma unroll
        for (int kk = 0; kk < 4; kk++) {
            uint32_t vf[4][4];
#pragma unroll
            for (int nc = 0; nc < 4; nc++)
                LDM_X4T(vf[nc], sb + vOff + (uint32_t)(kk*16*ATT_PITCH)*2 + nc*32);
#pragma unroll
            for (int nc = 0; nc < 4; nc++) {
                MMA16816(o[2*nc],   pah[kk], vf[nc]);
                MMA16816(o[2*nc+1], pah[kk], vf[nc]+2);
            }
        }

        }
    }

    // ---- epilogue: y hi-only ----
    const float inv0 = 1.f / l0, inv1 = 1.f / l1;
    const int r0 = row_lo, r1 = row_lo + 8;
#pragma unroll
    for (int n = 0; n < 8; n++) {
        const int d = n*8 + 2*(lane & 3);
        const size_t y0 = ((size_t)(b*T_ + r0))*C_ + h*D_ + d;
        const size_t y1 = ((size_t)(b*T_ + r1))*C_ + h*D_ + d;
        *(uint32_t*)&g_yh[y0] = pack_h2(o[n][0]*inv0, o[n][1]*inv0);
        *(uint32_t*)&g_yh[y1] = pack_h2(o[n][2]*inv1, o[n][3]*inv1);
    }
}

// -------------------------------------------------------------------------------
extern "C" void kernel_launch(void* const* d_in, const int* in_sizes, int n_in,
                              void* d_out, int out_size)
{
    const float* x      = (const float*)d_in[0];
    const float* w_attn = (const float*)d_in[1];
    const float* b_attn = (const float*)d_in[2];
    const float* w_proj = (const float*)d_in[3];
    const float* b_proj = (const float*)d_in[4];
    float* out = (float*)d_out;

    cudaFuncSetAttribute(gemm_fp16<true>,
        cudaFuncAttributeMaxDynamicSharedMemorySize, GEMM_SMEM);
    cudaFuncSetAttribute(gemm_fp16<false>,
        cudaFuncAttributeMaxDynamicSharedMemorySize, GEMM_SMEM);
    cudaFuncSetAttribute(attn_mma_kernel,
        cudaFuncAttributeMaxDynamicSharedMemorySize, ATT_SMEM);

    {
        int total = NX + NWA + NWP;
        preprocess_kernel<<<(total + 255) / 256, 256>>>(x, w_attn, w_proj);
    }

    dim3 g1(3 * C_ / BN, M_ / BM);   // (24, 64)
    gemm_fp16<true><<<g1, 256, GEMM_SMEM>>>(b_attn, nullptr);

    dim3 g2(T_ / 128, H_, B_);       // (16, 16, 4)
    attn_mma_kernel<<<g2, 256, ATT_SMEM>>>();

    dim3 g3(C_ / BN, M_ / BM);       // (8, 64)
    gemm_fp16<false><<<g3, 256, GEMM_SMEM>>>(b_proj, out);
}

// round 15
// speedup vs baseline: 1.5039x; 1.0176x over previous
#include <cuda_runtime.h>
#include <cuda_fp16.h>
#include <cstdint>

#define B_ 4
#define T_ 2048
#define C_ 1024
#define H_ 16
#define D_ 64
#define M_ (B_*T_)   /* 8192 */

// ---------------- device scratch (fp16) ----------------------------------------
__device__ __half g_x[(size_t)M_*C_];
__device__ __half g_wa[(size_t)C_*3*C_];
__device__ __half g_wp[(size_t)C_*C_];
__device__ __half g_yh[(size_t)M_*C_];
__device__ __half g_q[(size_t)M_*C_];
__device__ __half g_k[(size_t)M_*C_];
__device__ __half g_v[(size_t)M_*C_];

// ---------------- helpers ------------------------------------------------------
__device__ __forceinline__ uint32_t s2u(const void* p) {
    return (uint32_t)__cvta_generic_to_shared(p);
}
__device__ __forceinline__ void cpa16(uint32_t dst, const void* src) {
    asm volatile("cp.async.cg.shared.global [%0], [%1], 16;" :: "r"(dst), "l"(src));
}
#define CP_COMMIT() asm volatile("cp.async.commit_group;" ::: "memory")
#define CP_WAIT0()  asm volatile("cp.async.wait_group 0;" ::: "memory")
#define CP_WAIT2()  asm volatile("cp.async.wait_group 2;" ::: "memory")

#define LDM_X4(r, addr) \
    asm volatile("ldmatrix.sync.aligned.m8n8.x4.shared.b16 {%0,%1,%2,%3},[%4];" \
        : "=r"((r)[0]), "=r"((r)[1]), "=r"((r)[2]), "=r"((r)[3]) : "r"(addr))
#define LDM_X4T(r, addr) \
    asm volatile("ldmatrix.sync.aligned.m8n8.x4.trans.shared.b16 {%0,%1,%2,%3},[%4];" \
        : "=r"((r)[0]), "=r"((r)[1]), "=r"((r)[2]), "=r"((r)[3]) : "r"(addr))

#define MMA16816(d, a, b) \
    asm volatile("mma.sync.aligned.m16n8k16.row.col.f32.f16.f16.f32 " \
        "{%0,%1,%2,%3},{%4,%5,%6,%7},{%8,%9},{%0,%1,%2,%3};" \
        : "+f"((d)[0]), "+f"((d)[1]), "+f"((d)[2]), "+f"((d)[3]) \
        : "r"((a)[0]), "r"((a)[1]), "r"((a)[2]), "r"((a)[3]), \
          "r"((b)[0]), "r"((b)[1]))

__device__ __forceinline__ float ex2f(float x) {
    float y;
    asm("ex2.approx.f32 %0, %1;" : "=f"(y) : "f"(x));
    return y;
}

__device__ __forceinline__ uint32_t pack_h2(float a, float b) {
    __half2 v = __floats2half2_rn(a, b);
    return *(uint32_t*)&v;
}

// q pre-scale: 1/sqrt(D) * log2(e)
#define QSCALE 0.1803368801111306f

// ---------------- merged preprocessing (8 fp32 -> 8 fp16 per thread) ------------
#define NX8  (M_*C_/8)
#define NWA8 (3*C_*C_/8)
#define NWP8 (C_*C_/8)

__global__ void preprocess_kernel(const float* __restrict__ x,
                                  const float* __restrict__ wa,
                                  const float* __restrict__ wp)
{
    int i = blockIdx.x * blockDim.x + threadIdx.x;
    const float* src;
    __half* dst;
    int j;
    if (i < NX8)                  { src = x;  dst = g_x;  j = i; }
    else if (i < NX8 + NWA8)      { src = wa; dst = g_wa; j = i - NX8; }
    else if (i < NX8 + NWA8 + NWP8){ src = wp; dst = g_wp; j = i - NX8 - NWA8; }
    else return;
    float4 v0 = ((const float4*)src)[2*j];
    float4 v1 = ((const float4*)src)[2*j + 1];
    ((uint4*)dst)[j] = make_uint4(pack_h2(v0.x, v0.y), pack_h2(v0.z, v0.w),
                                  pack_h2(v1.x, v1.y), pack_h2(v1.z, v1.w));
}

// ---------------- fp16 GEMM, 1-product, BK=16, 4-stage (R14-measured) -----------
#define BM 128
#define BN 128
#define BK 16
#define AST 24
#define BST 136
#define KTILES (C_/BK)          /* 64 */
#define STAGES 4
#define ASZ (BM*AST*2)
#define BSZ (BK*BST*2)
#define STG (ASZ + BSZ)
#define GEMM_SMEM (STAGES*STG)  /* 41984 B */

template<bool SCATTER>
__global__ __launch_bounds__(256, 2) void gemm_fp16(
    const float* __restrict__ bias, float* __restrict__ out)
{
    extern __shared__ char dsm[];
    const uint32_t base = s2u(dsm);

    const __half* Ag = SCATTER ? g_x : g_yh;
    const __half* Bg = SCATTER ? g_wa : g_wp;
    const int NSTR = SCATTER ? 3*C_ : C_;

    const int K = C_;
    const int tid  = threadIdx.x;
    const int lane = tid & 31, wid = tid >> 5;
    const int wr = wid >> 1, wc = wid & 1;
    const int row0 = blockIdx.y * BM, col0 = blockIdx.x * BN;

    const int rA = tid >> 1, cA = tid & 1;
    const int rB = tid >> 4, cB = tid & 15;

    const __half* srcA = Ag + (size_t)(row0 + rA) * K + cA * 8;
    const __half* srcB = Bg + (size_t)rB * NSTR + col0 + cB * 8;

    const uint32_t offA = (uint32_t)(rA*AST + cA*8) * 2;
    const uint32_t offB = (uint32_t)(rB*BST + cB*8) * 2;

    auto load_stage = [&](int kt, int buf) {
        const uint32_t sb = base + buf * STG;
        cpa16(sb + offA, srcA + kt * BK);
        cpa16(sb + ASZ + offB, srcB + (size_t)kt * BK * NSTR);
    };

    const int lm = lane & 15, lh = lane >> 4;
    const uint32_t aOff = (uint32_t)((wr*32 + lm) * AST + lh * 8) * 2;
    const uint32_t bOff = (uint32_t)(lm * BST + (wc*64 + lh*8)) * 2;

    float acc[2][8][4];
#pragma unroll
    for (int mi = 0; mi < 2; mi++)
#pragma unroll
        for (int ni = 0; ni < 8; ni++)
#pragma unroll
            for (int r = 0; r < 4; r++) acc[mi][ni][r] = 0.f;

    auto compute = [&](int buf) {
        const uint32_t sb = base + buf * STG;
        const uint32_t aA = sb + aOff;
        const uint32_t bB = sb + ASZ + bOff;
        uint32_t aa[2][4], bb[8][2], r[4];
#pragma unroll
        for (int mi = 0; mi < 2; mi++) LDM_X4(aa[mi], aA + mi * (16*AST*2));
#pragma unroll
        for (int g = 0; g < 4; g++) {
            LDM_X4T(r, bB + g * 32);
            bb[2*g][0]   = r[0]; bb[2*g][1]   = r[1];
            bb[2*g+1][0] = r[2]; bb[2*g+1][1] = r[3];
        }
#pragma unroll
        for (int mi = 0; mi < 2; mi++)
#pragma unroll
            for (int ni = 0; ni < 8; ni++) MMA16816(acc[mi][ni], aa[mi], bb[ni]);
    };

#pragma unroll
    for (int s = 0; s < STAGES - 1; s++) {
        load_stage(s, s);
        CP_COMMIT();
    }

#pragma unroll 1
    for (int kt = 0; kt < KTILES; kt++) {
        CP_WAIT2();
        __syncthreads();
        if (kt + STAGES - 1 < KTILES)
            load_stage(kt + STAGES - 1, (kt + STAGES - 1) & (STAGES - 1));
        CP_COMMIT();
        compute(kt & (STAGES - 1));
    }

    // ---------------- epilogue ----------------
    const int ncol0 = col0 + wc * 64;

#pragma unroll
    for (int ni = 0; ni < 8; ni++) {
        const int n = ncol0 + ni*8 + (lane & 3) * 2;
        const float b0 = bias[n], b1 = bias[n + 1];
        if (SCATTER) {
            const int which = n / C_;
            const int c0 = n % C_;
            const int hh = c0 / D_, d0 = c0 % D_;
            const float sc = (which == 0) ? QSCALE : 1.0f;
            __half* dst = (which == 0) ? g_q : (which == 1) ? g_k : g_v;
#pragma unroll
            for (int mi = 0; mi < 2; mi++) {
                const int m = row0 + wr*32 + mi*16 + (lane >> 2);
                const int b = m / T_, t = m % T_;
                const size_t bse = (((size_t)(b*H_ + hh)) * T_ + t) * D_ + d0;
                *(uint32_t*)&dst[bse] =
                    pack_h2((acc[mi][ni][0] + b0) * sc, (acc[mi][ni][1] + b1) * sc);
                *(uint32_t*)&dst[bse + 8*D_] =
                    pack_h2((acc[mi][ni][2] + b0) * sc, (acc[mi][ni][3] + b1) * sc);
            }
        } else {
#pragma unroll
            for (int mi = 0; mi < 2; mi++) {
                const int m = row0 + wr*32 + mi*16 + (lane >> 2);
                *(float2*)&out[(size_t)m * C_ + n] =
                    make_float2(acc[mi][ni][0] + b0, acc[mi][ni][1] + b1);
                *(float2*)&out[(size_t)(m + 8) * C_ + n] =
                    make_float2(acc[mi][ni][2] + b0, acc[mi][ni][3] + b1);
            }
        }
    }
}

// ---------------- fp16 flash attention: deferred l-reduce, skip-rescale ---------
#define ATT_PITCH 72
#define KV_ARR (64*ATT_PITCH*2)
#define KV_STG (2*KV_ARR)
#define ATT_SMEM (2*KV_STG)

__global__ __launch_bounds__(256, 2) void attn_mma_kernel()
{
    extern __shared__ char dsm[];
    const uint32_t base = s2u(dsm);
    __half* smp = (__half*)dsm;

    const int b = blockIdx.z, h = blockIdx.y;
    const int qt = gridDim.x - 1 - blockIdx.x;   // longest-first
    const int q0 = qt * 128;
    const int tid = threadIdx.x, lane = tid & 31, wid = tid >> 5;
    const size_t hb = ((size_t)(b*H_ + h)) * T_ * D_;

    {
        const int row = tid >> 1, cg = (tid & 1) * 32;
        const uint4* s4 = (const uint4*)(g_q + hb + (size_t)(q0+row)*D_ + cg);
        uint4* d4 = (uint4*)(smp + row*ATT_PITCH + cg);
#pragma unroll
        for (int i = 0; i < 4; i++) d4[i] = s4[i];
    }
    __syncthreads();

    uint32_t qf[4][4];
    {
        const int qr = lane & 15, qc = (lane & 16) >> 1;
        const uint32_t baseQ = base + (uint32_t)((wid*16 + qr)*ATT_PITCH + qc) * 2;
#pragma unroll
        for (int kk = 0; kk < 4; kk++)
            LDM_X4(qf[kk], baseQ + kk * 32);
    }
    __syncthreads();

    float o[8][4];
#pragma unroll
    for (int n = 0; n < 8; n++)
#pragma unroll
        for (int r = 0; r < 4; r++) o[n][r] = 0.f;
    float m0 = -1e30f, m1 = -1e30f;
    float lp0 = 0.f, lp1 = 0.f;   // per-thread partial row sums (reduced at end)

    const int kbrow = (lane & 7) + ((lane & 16) >> 1);
    const int kbcol = (lane & 8);
    const int vrow  = lane & 15;
    const int vcolg = (lane & 16) >> 1;
    const uint32_t kOff = (uint32_t)(kbrow*ATT_PITCH + kbcol) * 2;
    const uint32_t vOff = KV_ARR + (uint32_t)(vrow*ATT_PITCH + vcolg) * 2;

    const int kvr = tid >> 3, kvc = (tid & 7) * 8;
    const uint32_t dOff = (uint32_t)(kvr*ATT_PITCH + kvc) * 2;
    const uint32_t rstep = 32*ATT_PITCH*2;

    auto load_tile = [&](int k0, int buf) {
        const uint32_t sb = base + buf * KV_STG;
        const size_t g = hb + (size_t)(k0 + kvr)*D_ + kvc;
        cpa16(sb + dOff,                  g_k + g);
        cpa16(sb + dOff + rstep,          g_k + g + 32*D_);
        cpa16(sb + KV_ARR + dOff,         g_v + g);
        cpa16(sb + KV_ARR + dOff + rstep, g_v + g + 32*D_);
    };

    const int row_lo = q0 + wid*16 + (lane >> 2);
    const int row_hi_warp = q0 + wid*16 + 15;
    const int ntiles = q0/64 + 2;

    load_tile(0, 0);
    CP_COMMIT();

#pragma unroll 1
    for (int t = 0; t < ntiles; t++) {
        const int k0 = t * 64;
        const uint32_t sb = base + (t & 1) * KV_STG;

        CP_WAIT0();
        __syncthreads();
        if (t + 1 < ntiles) {
            load_tile(k0 + 64, (t + 1) & 1);
            CP_COMMIT();
        }

        if (k0 <= row_hi_warp) {

        float s[8][4];
#pragma unroll
        for (int n = 0; n < 8; n++)
#pragma unroll
            for (int r = 0; r < 4; r++) s[n][r] = 0.f;

#pragma unroll
        for (int kk = 0; kk < 4; kk++) {
            uint32_t kf[4][4];
#pragma unroll
            for (int np = 0; np < 4; np++)
                LDM_X4(kf[np], sb + kOff + (uint32_t)(np*16*ATT_PITCH)*2 + kk*32);
#pragma unroll
            for (int np = 0; np < 4; np++) {
                MMA16816(s[2*np],   qf[kk], kf[np]);
                MMA16816(s[2*np+1], qf[kk], kf[np]+2);
            }
        }

        if (k0 + 64 > q0) {
#pragma unroll
            for (int n = 0; n < 8; n++) {
                const int c = k0 + n*8 + 2*(lane & 3);
                if (c     > row_lo)     s[n][0] = -1e30f;
                if (c + 1 > row_lo)     s[n][1] = -1e30f;
                if (c     > row_lo + 8) s[n][2] = -1e30f;
                if (c + 1 > row_lo + 8) s[n][3] = -1e30f;
            }
        }

        float tm0 = -1e30f, tm1 = -1e30f;
#pragma unroll
        for (int n = 0; n < 8; n++) {
            tm0 = fmaxf(tm0, fmaxf(s[n][0], s[n][1]));
            tm1 = fmaxf(tm1, fmaxf(s[n][2], s[n][3]));
        }
        tm0 = fmaxf(tm0, __shfl_xor_sync(0xffffffff, tm0, 1));
        tm0 = fmaxf(tm0, __shfl_xor_sync(0xffffffff, tm0, 2));
        tm1 = fmaxf(tm1, __shfl_xor_sync(0xffffffff, tm1, 1));
        tm1 = fmaxf(tm1, __shfl_xor_sync(0xffffffff, tm1, 2));

        // rescale only when running max changes (c == 1.0 exactly otherwise)
        if (tm0 > m0) {
            const float c0 = ex2f(m0 - tm0);
            m0 = tm0;
            lp0 *= c0;
#pragma unroll
            for (int n = 0; n < 8; n++) { o[n][0] *= c0; o[n][1] *= c0; }
        }
        if (tm1 > m1) {
            const float c1 = ex2f(m1 - tm1);
            m1 = tm1;
            lp1 *= c1;
#pragma unroll
            for (int n = 0; n < 8; n++) { o[n][2] *= c1; o[n][3] *= c1; }
        }

#pragma unroll
        for (int n = 0; n < 8; n++) {
            s[n][0] = ex2f(s[n][0] - m0);
            s[n][1] = ex2f(s[n][1] - m0);
            s[n][2] = ex2f(s[n][2] - m1);
            s[n][3] = ex2f(s[n][3] - m1);
            lp0 += s[n][0] + s[n][1];
            lp1 += s[n][2] + s[n][3];
        }

        uint32_t pah[4][4];
#pragma unroll
        for (int j = 0; j < 4; j++) {
            pah[j][0] = pack_h2(s[2*j][0],   s[2*j][1]);
            pah[j][1] = pack_h2(s[2*j][2],   s[2*j][3]);
            pah[j][2] = pack_h2(s[2*j+1][0], s[2*j+1][1]);
            pah[j][3] = pack_h2(s[2*j+1][2], s[2*j+1][3]);
        }

#pragma unroll
        for (int kk = 0; kk < 4; kk++) {
            uint32_t vf[4][4];
#pragma unroll
            for (int nc = 0; nc < 4; nc++)
                LDM_X4T(vf[nc], sb + vOff + (uint32_t)(kk*16*ATT_PITCH)*2 + nc*32);
#pragma unroll
            for (int nc = 0; nc < 4; nc++) {
                MMA16816(o[2*nc],   pah[kk], vf[nc]);
                MMA16816(o[2*nc+1], pah[kk], vf[nc]+2);
            }
        }

        }
    }

    // ---- final l reduction (once) + epilogue ----
    float l0 = lp0 + __shfl_xor_sync(0xffffffff, lp0, 1);
    l0 += __shfl_xor_sync(0xffffffff, l0, 2);
    float l1 = lp1 + __shfl_xor_sync(0xffffffff, lp1, 1);
    l1 += __shfl_xor_sync(0xffffffff, l1, 2);

    const float inv0 = 1.f / l0, inv1 = 1.f / l1;
    const int r0 = row_lo, r1 = row_lo + 8;
#pragma unroll
    for (int n = 0; n < 8; n++) {
        const int d = n*8 + 2*(lane & 3);
        const size_t y0 = ((size_t)(b*T_ + r0))*C_ + h*D_ + d;
        const size_t y1 = ((size_t)(b*T_ + r1))*C_ + h*D_ + d;
        *(uint32_t*)&g_yh[y0] = pack_h2(o[n][0]*inv0, o[n][1]*inv0);
        *(uint32_t*)&g_yh[y1] = pack_h2(o[n][2]*inv1, o[n][3]*inv1);
    }
}

// -------------------------------------------------------------------------------
extern "C" void kernel_launch(void* const* d_in, const int* in_sizes, int n_in,
                              void* d_out, int out_size)
{
    const float* x      = (const float*)d_in[0];
    const float* w_attn = (const float*)d_in[1];
    const float* b_attn = (const float*)d_in[2];
    const float* w_proj = (const float*)d_in[3];
    const float* b_proj = (const float*)d_in[4];
    float* out = (float*)d_out;

    cudaFuncSetAttribute(gemm_fp16<true>,
        cudaFuncAttributeMaxDynamicSharedMemorySize, GEMM_SMEM);
    cudaFuncSetAttribute(gemm_fp16<false>,
        cudaFuncAttributeMaxDynamicSharedMemorySize, GEMM_SMEM);
    cudaFuncSetAttribute(attn_mma_kernel,
        cudaFuncAttributeMaxDynamicSharedMemorySize, ATT_SMEM);

    {
        int total = NX8 + NWA8 + NWP8;
        preprocess_kernel<<<(total + 255) / 256, 256>>>(x, w_attn, w_proj);
    }

    dim3 g1(3 * C_ / BN, M_ / BM);   // (24, 64)
    gemm_fp16<true><<<g1, 256, GEMM_SMEM>>>(b_attn, nullptr);

    dim3 g2(T_ / 128, H_, B_);       // (16, 16, 4)
    attn_mma_kernel<<<g2, 256, ATT_SMEM>>>();

    dim3 g3(C_ / BN, M_ / BM);       // (8, 64)
    gemm_fp16<false><<<g3, 256, GEMM_SMEM>>>(b_proj, out);
}

// round 16
// speedup vs baseline: 1.5419x; 1.0253x over previous
#include <cuda_runtime.h>
#include <cuda_fp16.h>
#include <cstdint>

#define B_ 4
#define T_ 2048
#define C_ 1024
#define H_ 16
#define D_ 64
#define M_ (B_*T_)   /* 8192 */

// ---------------- device scratch (fp16) ----------------------------------------
__device__ __half g_x[(size_t)M_*C_];
__device__ __half g_wa[(size_t)C_*3*C_];
__device__ __half g_wp[(size_t)C_*C_];
__device__ __half g_yh[(size_t)M_*C_];
__device__ __half g_q[(size_t)M_*C_];
__device__ __half g_k[(size_t)M_*C_];
__device__ __half g_v[(size_t)M_*C_];

// ---------------- helpers ------------------------------------------------------
__device__ __forceinline__ uint32_t s2u(const void* p) {
    return (uint32_t)__cvta_generic_to_shared(p);
}
__device__ __forceinline__ void cpa16(uint32_t dst, const void* src) {
    asm volatile("cp.async.cg.shared.global [%0], [%1], 16;" :: "r"(dst), "l"(src));
}
#define CP_COMMIT() asm volatile("cp.async.commit_group;" ::: "memory")
#define CP_WAIT0()  asm volatile("cp.async.wait_group 0;" ::: "memory")
#define CP_WAIT2()  asm volatile("cp.async.wait_group 2;" ::: "memory")

#define LDM_X4(r, addr) \
    asm volatile("ldmatrix.sync.aligned.m8n8.x4.shared.b16 {%0,%1,%2,%3},[%4];" \
        : "=r"((r)[0]), "=r"((r)[1]), "=r"((r)[2]), "=r"((r)[3]) : "r"(addr))
#define LDM_X4T(r, addr) \
    asm volatile("ldmatrix.sync.aligned.m8n8.x4.trans.shared.b16 {%0,%1,%2,%3},[%4];" \
        : "=r"((r)[0]), "=r"((r)[1]), "=r"((r)[2]), "=r"((r)[3]) : "r"(addr))

#define MMA16816(d, a, b) \
    asm volatile("mma.sync.aligned.m16n8k16.row.col.f32.f16.f16.f32 " \
        "{%0,%1,%2,%3},{%4,%5,%6,%7},{%8,%9},{%0,%1,%2,%3};" \
        : "+f"((d)[0]), "+f"((d)[1]), "+f"((d)[2]), "+f"((d)[3]) \
        : "r"((a)[0]), "r"((a)[1]), "r"((a)[2]), "r"((a)[3]), \
          "r"((b)[0]), "r"((b)[1]))

__device__ __forceinline__ float ex2f(float x) {
    float y;
    asm("ex2.approx.f32 %0, %1;" : "=f"(y) : "f"(x));
    return y;
}
__device__ __forceinline__ uint32_t ex2h2(uint32_t x) {
    uint32_t y;
    asm("ex2.approx.f16x2 %0, %1;" : "=r"(y) : "r"(x));
    return y;
}

__device__ __forceinline__ uint32_t pack_h2(float a, float b) {
    __half2 v = __floats2half2_rn(a, b);
    return *(uint32_t*)&v;
}

// q pre-scale: 1/sqrt(D) * log2(e)
#define QSCALE 0.1803368801111306f

// ---------------- merged preprocessing (8 fp32 -> 8 fp16 per thread) ------------
#define NX8  (M_*C_/8)
#define NWA8 (3*C_*C_/8)
#define NWP8 (C_*C_/8)

__global__ void preprocess_kernel(const float* __restrict__ x,
                                  const float* __restrict__ wa,
                                  const float* __restrict__ wp)
{
    int i = blockIdx.x * blockDim.x + threadIdx.x;
    const float* src;
    __half* dst;
    int j;
    if (i < NX8)                  { src = x;  dst = g_x;  j = i; }
    else if (i < NX8 + NWA8)      { src = wa; dst = g_wa; j = i - NX8; }
    else if (i < NX8 + NWA8 + NWP8){ src = wp; dst = g_wp; j = i - NX8 - NWA8; }
    else return;
    float4 v0 = ((const float4*)src)[2*j];
    float4 v1 = ((const float4*)src)[2*j + 1];
    ((uint4*)dst)[j] = make_uint4(pack_h2(v0.x, v0.y), pack_h2(v0.z, v0.w),
                                  pack_h2(v1.x, v1.y), pack_h2(v1.z, v1.w));
}

// ---------------- fp16 GEMM, 1-product, BK=16, 4-stage (R14-measured) -----------
#define BM 128
#define BN 128
#define BK 16
#define AST 24
#define BST 136
#define KTILES (C_/BK)          /* 64 */
#define STAGES 4
#define ASZ (BM*AST*2)
#define BSZ (BK*BST*2)
#define STG (ASZ + BSZ)
#define GEMM_SMEM (STAGES*STG)  /* 41984 B */

template<bool SCATTER>
__global__ __launch_bounds__(256, 2) void gemm_fp16(
    const float* __restrict__ bias, float* __restrict__ out)
{
    extern __shared__ char dsm[];
    const uint32_t base = s2u(dsm);

    const __half* Ag = SCATTER ? g_x : g_yh;
    const __half* Bg = SCATTER ? g_wa : g_wp;
    const int NSTR = SCATTER ? 3*C_ : C_;

    const int K = C_;
    const int tid  = threadIdx.x;
    const int lane = tid & 31, wid = tid >> 5;
    const int wr = wid >> 1, wc = wid & 1;
    const int row0 = blockIdx.y * BM, col0 = blockIdx.x * BN;

    const int rA = tid >> 1, cA = tid & 1;
    const int rB = tid >> 4, cB = tid & 15;

    const __half* srcA = Ag + (size_t)(row0 + rA) * K + cA * 8;
    const __half* srcB = Bg + (size_t)rB * NSTR + col0 + cB * 8;

    const uint32_t offA = (uint32_t)(rA*AST + cA*8) * 2;
    const uint32_t offB = (uint32_t)(rB*BST + cB*8) * 2;

    auto load_stage = [&](int kt, int buf) {
        const uint32_t sb = base + buf * STG;
        cpa16(sb + offA, srcA + kt * BK);
        cpa16(sb + ASZ + offB, srcB + (size_t)kt * BK * NSTR);
    };

    const int lm = lane & 15, lh = lane >> 4;
    const uint32_t aOff = (uint32_t)((wr*32 + lm) * AST + lh * 8) * 2;
    const uint32_t bOff = (uint32_t)(lm * BST + (wc*64 + lh*8)) * 2;

    float acc[2][8][4];
#pragma unroll
    for (int mi = 0; mi < 2; mi++)
#pragma unroll
        for (int ni = 0; ni < 8; ni++)
#pragma unroll
            for (int r = 0; r < 4; r++) acc[mi][ni][r] = 0.f;

    auto compute = [&](int buf) {
        const uint32_t sb = base + buf * STG;
        const uint32_t aA = sb + aOff;
        const uint32_t bB = sb + ASZ + bOff;
        uint32_t aa[2][4], bb[8][2], r[4];
#pragma unroll
        for (int mi = 0; mi < 2; mi++) LDM_X4(aa[mi], aA + mi * (16*AST*2));
#pragma unroll
        for (int g = 0; g < 4; g++) {
            LDM_X4T(r, bB + g * 32);
            bb[2*g][0]   = r[0]; bb[2*g][1]   = r[1];
            bb[2*g+1][0] = r[2]; bb[2*g+1][1] = r[3];
        }
#pragma unroll
        for (int mi = 0; mi < 2; mi++)
#pragma unroll
            for (int ni = 0; ni < 8; ni++) MMA16816(acc[mi][ni], aa[mi], bb[ni]);
    };

#pragma unroll
    for (int s = 0; s < STAGES - 1; s++) {
        load_stage(s, s);
        CP_COMMIT();
    }

#pragma unroll 1
    for (int kt = 0; kt < KTILES; kt++) {
        CP_WAIT2();
        __syncthreads();
        if (kt + STAGES - 1 < KTILES)
            load_stage(kt + STAGES - 1, (kt + STAGES - 1) & (STAGES - 1));
        CP_COMMIT();
        compute(kt & (STAGES - 1));
    }

    // ---------------- epilogue ----------------
    const int ncol0 = col0 + wc * 64;

#pragma unroll
    for (int ni = 0; ni < 8; ni++) {
        const int n = ncol0 + ni*8 + (lane & 3) * 2;
        const float b0 = bias[n], b1 = bias[n + 1];
        if (SCATTER) {
            const int which = n / C_;
            const int c0 = n % C_;
            const int hh = c0 / D_, d0 = c0 % D_;
            const float sc = (which == 0) ? QSCALE : 1.0f;
            __half* dst = (which == 0) ? g_q : (which == 1) ? g_k : g_v;
#pragma unroll
            for (int mi = 0; mi < 2; mi++) {
                const int m = row0 + wr*32 + mi*16 + (lane >> 2);
                const int b = m / T_, t = m % T_;
                const size_t bse = (((size_t)(b*H_ + hh)) * T_ + t) * D_ + d0;
                *(uint32_t*)&dst[bse] =
                    pack_h2((acc[mi][ni][0] + b0) * sc, (acc[mi][ni][1] + b1) * sc);
                *(uint32_t*)&dst[bse + 8*D_] =
                    pack_h2((acc[mi][ni][2] + b0) * sc, (acc[mi][ni][3] + b1) * sc);
            }
        } else {
#pragma unroll
            for (int mi = 0; mi < 2; mi++) {
                const int m = row0 + wr*32 + mi*16 + (lane >> 2);
                *(float2*)&out[(size_t)m * C_ + n] =
                    make_float2(acc[mi][ni][0] + b0, acc[mi][ni][1] + b1);
                *(float2*)&out[(size_t)(m + 8) * C_ + n] =
                    make_float2(acc[mi][ni][2] + b0, acc[mi][ni][3] + b1);
            }
        }
    }
}

// ---------------- fp16 flash attention: f16x2 exp + ones-MMA l-sum --------------
#define ATT_PITCH 72
#define KV_ARR (64*ATT_PITCH*2)
#define KV_STG (2*KV_ARR)
#define ATT_SMEM (2*KV_STG)

__global__ __launch_bounds__(256, 2) void attn_mma_kernel()
{
    extern __shared__ char dsm[];
    const uint32_t base = s2u(dsm);
    __half* smp = (__half*)dsm;

    const int b = blockIdx.z, h = blockIdx.y;
    const int qt = gridDim.x - 1 - blockIdx.x;   // longest-first
    const int q0 = qt * 128;
    const int tid = threadIdx.x, lane = tid & 31, wid = tid >> 5;
    const size_t hb = ((size_t)(b*H_ + h)) * T_ * D_;

    {
        const int row = tid >> 1, cg = (tid & 1) * 32;
        const uint4* s4 = (const uint4*)(g_q + hb + (size_t)(q0+row)*D_ + cg);
        uint4* d4 = (uint4*)(smp + row*ATT_PITCH + cg);
#pragma unroll
        for (int i = 0; i < 4; i++) d4[i] = s4[i];
    }
    __syncthreads();

    uint32_t qf[4][4];
    {
        const int qr = lane & 15, qc = (lane & 16) >> 1;
        const uint32_t baseQ = base + (uint32_t)((wid*16 + qr)*ATT_PITCH + qc) * 2;
#pragma unroll
        for (int kk = 0; kk < 4; kk++)
            LDM_X4(qf[kk], baseQ + kk * 32);
    }
    __syncthreads();

    float o[8][4];
#pragma unroll
    for (int n = 0; n < 8; n++)
#pragma unroll
        for (int r = 0; r < 4; r++) o[n][r] = 0.f;
    float la[4] = {0.f, 0.f, 0.f, 0.f};   // l via ones-MMA ([0]=row, [2]=row+8)
    float m0 = -1e30f, m1 = -1e30f;
    const uint32_t ones2[2] = {0x3C003C00u, 0x3C003C00u};  // {1h,1h},{1h,1h}

    const int kbrow = (lane & 7) + ((lane & 16) >> 1);
    const int kbcol = (lane & 8);
    const int vrow  = lane & 15;
    const int vcolg = (lane & 16) >> 1;
    const uint32_t kOff = (uint32_t)(kbrow*ATT_PITCH + kbcol) * 2;
    const uint32_t vOff = KV_ARR + (uint32_t)(vrow*ATT_PITCH + vcolg) * 2;

    const int kvr = tid >> 3, kvc = (tid & 7) * 8;
    const uint32_t dOff = (uint32_t)(kvr*ATT_PITCH + kvc) * 2;
    const uint32_t rstep = 32*ATT_PITCH*2;

    auto load_tile = [&](int k0, int buf) {
        const uint32_t sb = base + buf * KV_STG;
        const size_t g = hb + (size_t)(k0 + kvr)*D_ + kvc;
        cpa16(sb + dOff,                  g_k + g);
        cpa16(sb + dOff + rstep,          g_k + g + 32*D_);
        cpa16(sb + KV_ARR + dOff,         g_v + g);
        cpa16(sb + KV_ARR + dOff + rstep, g_v + g + 32*D_);
    };

    const int row_lo = q0 + wid*16 + (lane >> 2);
    const int row_hi_warp = q0 + wid*16 + 15;
    const int ntiles = q0/64 + 2;

    load_tile(0, 0);
    CP_COMMIT();

#pragma unroll 1
    for (int t = 0; t < ntiles; t++) {
        const int k0 = t * 64;
        const uint32_t sb = base + (t & 1) * KV_STG;

        CP_WAIT0();
        __syncthreads();
        if (t + 1 < ntiles) {
            load_tile(k0 + 64, (t + 1) & 1);
            CP_COMMIT();
        }

        if (k0 <= row_hi_warp) {

        float s[8][4];
#pragma unroll
        for (int n = 0; n < 8; n++)
#pragma unroll
            for (int r = 0; r < 4; r++) s[n][r] = 0.f;

#pragma unroll
        for (int kk = 0; kk < 4; kk++) {
            uint32_t kf[4][4];
#pragma unroll
            for (int np = 0; np < 4; np++)
                LDM_X4(kf[np], sb + kOff + (uint32_t)(np*16*ATT_PITCH)*2 + kk*32);
#pragma unroll
            for (int np = 0; np < 4; np++) {
                MMA16816(s[2*np],   qf[kk], kf[np]);
                MMA16816(s[2*np+1], qf[kk], kf[np]+2);
            }
        }

        if (k0 + 64 > q0) {
#pragma unroll
            for (int n = 0; n < 8; n++) {
                const int c = k0 + n*8 + 2*(lane & 3);
                if (c     > row_lo)     s[n][0] = -1e30f;
                if (c + 1 > row_lo)     s[n][1] = -1e30f;
                if (c     > row_lo + 8) s[n][2] = -1e30f;
                if (c + 1 > row_lo + 8) s[n][3] = -1e30f;
            }
        }

        float tm0 = -1e30f, tm1 = -1e30f;
#pragma unroll
        for (int n = 0; n < 8; n++) {
            tm0 = fmaxf(tm0, fmaxf(s[n][0], s[n][1]));
            tm1 = fmaxf(tm1, fmaxf(s[n][2], s[n][3]));
        }
        tm0 = fmaxf(tm0, __shfl_xor_sync(0xffffffff, tm0, 1));
        tm0 = fmaxf(tm0, __shfl_xor_sync(0xffffffff, tm0, 2));
        tm1 = fmaxf(tm1, __shfl_xor_sync(0xffffffff, tm1, 1));
        tm1 = fmaxf(tm1, __shfl_xor_sync(0xffffffff, tm1, 2));

        if (tm0 > m0) {
            const float c0 = ex2f(m0 - tm0);
            m0 = tm0;
            la[0] *= c0;
#pragma unroll
            for (int n = 0; n < 8; n++) { o[n][0] *= c0; o[n][1] *= c0; }
        }
        if (tm1 > m1) {
            const float c1 = ex2f(m1 - tm1);
            m1 = tm1;
            la[2] *= c1;
#pragma unroll
            for (int n = 0; n < 8; n++) { o[n][2] *= c1; o[n][3] *= c1; }
        }

        // P = ex2(s - m) computed directly in packed fp16 (half the MUFU ops)
        uint32_t pah[4][4];
#pragma unroll
        for (int j = 0; j < 4; j++) {
            pah[j][0] = ex2h2(pack_h2(s[2*j][0]   - m0, s[2*j][1]   - m0));
            pah[j][1] = ex2h2(pack_h2(s[2*j][2]   - m1, s[2*j][3]   - m1));
            pah[j][2] = ex2h2(pack_h2(s[2*j+1][0] - m0, s[2*j+1][1] - m0));
            pah[j][3] = ex2h2(pack_h2(s[2*j+1][2] - m1, s[2*j+1][3] - m1));
        }

        // l += P @ ones (row sums in fp32 acc; every thread gets full row sum)
#pragma unroll
        for (int kk = 0; kk < 4; kk++)
            MMA16816(la, pah[kk], ones2);

#pragma unroll
        for (int kk = 0; kk < 4; kk++) {
            uint32_t vf[4][4];
#pragma unroll
            for (int nc = 0; nc < 4; nc++)
                LDM_X4T(vf[nc], sb + vOff + (uint32_t)(kk*16*ATT_PITCH)*2 + nc*32);
#pragma unroll
            for (int nc = 0; nc < 4; nc++) {
                MMA16816(o[2*nc],   pah[kk], vf[nc]);
                MMA16816(o[2*nc+1], pah[kk], vf[nc]+2);
            }
        }

        }
    }

    // ---- epilogue: l already complete per-thread (la[0]=row, la[2]=row+8) ----
    const float inv0 = 1.f / la[0], inv1 = 1.f / la[2];
    const int r0 = row_lo, r1 = row_lo + 8;
#pragma unroll
    for (int n = 0; n < 8; n++) {
        const int d = n*8 + 2*(lane & 3);
        const size_t y0 = ((size_t)(b*T_ + r0))*C_ + h*D_ + d;
        const size_t y1 = ((size_t)(b*T_ + r1))*C_ + h*D_ + d;
        *(uint32_t*)&g_yh[y0] = pack_h2(o[n][0]*inv0, o[n][1]*inv0);
        *(uint32_t*)&g_yh[y1] = pack_h2(o[n][2]*inv1, o[n][3]*inv1);
    }
}

// -------------------------------------------------------------------------------
extern "C" void kernel_launch(void* const* d_in, const int* in_sizes, int n_in,
                              void* d_out, int out_size)
{
    const float* x      = (const float*)d_in[0];
    const float* w_attn = (const float*)d_in[1];
    const float* b_attn = (const float*)d_in[2];
    const float* w_proj = (const float*)d_in[3];
    const float* b_proj = (const float*)d_in[4];
    float* out = (float*)d_out;

    cudaFuncSetAttribute(gemm_fp16<true>,
        cudaFuncAttributeMaxDynamicSharedMemorySize, GEMM_SMEM);
    cudaFuncSetAttribute(gemm_fp16<false>,
        cudaFuncAttributeMaxDynamicSharedMemorySize, GEMM_SMEM);
    cudaFuncSetAttribute(attn_mma_kernel,
        cudaFuncAttributeMaxDynamicSharedMemorySize, ATT_SMEM);

    {
        int total = NX8 + NWA8 + NWP8;
        preprocess_kernel<<<(total + 255) / 256, 256>>>(x, w_attn, w_proj);
    }

    dim3 g1(3 * C_ / BN, M_ / BM);   // (24, 64)
    gemm_fp16<true><<<g1, 256, GEMM_SMEM>>>(b_attn, nullptr);

    dim3 g2(T_ / 128, H_, B_);       // (16, 16, 4)
    attn_mma_kernel<<<g2, 256, ATT_SMEM>>>();

    dim3 g3(C_ / BN, M_ / BM);       // (8, 64)
    gemm_fp16<false><<<g3, 256, GEMM_SMEM>>>(b_proj, out);
}